// round 14
// baseline (speedup 1.0000x reference)
#include <cuda_runtime.h>
#include <cuda_bf16.h>
#include <cuda_fp16.h>
#include <math.h>
#include <stdint.h>

#define Bn 8
#define Tn 1024
#define Cn 2048
#define Hn 32
#define BT (Bn*Tn)                 // 8192
#define BTC ((size_t)BT*Cn)        // 16777216
#define LN_EPS (1e-5f*64.0f)
#define KP 128

typedef __nv_bfloat16 bf16;

// ---------------- scratch ----------------
__device__ float g_r[BTC], g_k[BTC], g_v[BTC], g_wdec[BTC], g_a[BTC], g_vg[BTC];
__device__ float g_g[BTC], g_nkk[BTC], g_ab[BTC], g_knew[BTC], g_y[BTC];
__device__ __align__(128) bf16 g_xkt[(size_t)BT*4096], g_xvt[(size_t)BT*4096];
__device__ __align__(128) bf16 g_xwt[(size_t)BT*4096], g_xat[(size_t)BT*4096], g_xgt[(size_t)BT*4096];
__device__ __align__(128) __half g_xrt16[(size_t)BT*2048];
__device__ __align__(128) __half g_ygt[(size_t)BT*2048];
__device__ __align__(128) bf16 g_Wt[2][(size_t)Cn*4096];          // Wk, Wv
__device__ __align__(128) __half g_Wr16[(size_t)Cn*2048];
__device__ __align__(128) __half g_Wo16[(size_t)Cn*2048];
__device__ __align__(128) bf16 g_w1bt[4][(size_t)64*8192];
__device__ __align__(128) bf16 g_w2t[4][(size_t)Cn*2*KP];
__device__ __align__(128) bf16 g_hid4[4][(size_t)BT*256];

// ---------------- helpers ----------------
__device__ __forceinline__ void split_store(bf16* dst, size_t hi_idx, size_t lo_off, float v) {
    bf16 hi = __float2bfloat16(v);
    bf16 lo = __float2bfloat16(v - __bfloat162float(hi));
    dst[hi_idx] = hi;
    dst[hi_idx + lo_off] = lo;
}

__device__ __forceinline__ uint32_t pack2(bf16 a, bf16 b) {
    return ((uint32_t)*(uint16_t*)&b << 16) | (uint32_t)*(uint16_t*)&a;
}

__device__ __forceinline__ void split_store2(bf16* dst, size_t hi_idx, size_t lo_off,
                                             float v0, float v1) {
    bf16 h0 = __float2bfloat16(v0), h1 = __float2bfloat16(v1);
    bf16 l0 = __float2bfloat16(v0 - __bfloat162float(h0));
    bf16 l1 = __float2bfloat16(v1 - __bfloat162float(h1));
    *(uint32_t*)&dst[hi_idx] = pack2(h0, h1);
    *(uint32_t*)&dst[hi_idx + lo_off] = pack2(l0, l1);
}

__device__ __forceinline__ size_t tile_idx8(int mb, int kt, int r, int cc) {
    int slot = (cc >> 3) ^ ((r >> 1) & 3);
    return ((size_t)(mb * 64 + kt)) * 8192 + r * 32 + slot * 8 + (cc & 7);
}
__device__ __forceinline__ size_t tile_idx4(int mb, int kt, int r, int cc) {
    int slot = (cc >> 3) ^ ((r >> 1) & 3);
    return ((size_t)(mb * 64 + kt)) * 4096 + r * 32 + slot * 8 + (cc & 7);
}

__device__ __forceinline__ uint32_t smem_u32(const void* p) {
    return (uint32_t)__cvta_generic_to_shared(p);
}

__device__ __forceinline__ uint64_t pkf2(float a, float b) {
    uint64_t r; asm("mov.b64 %0, {%1, %2};" : "=l"(r) : "f"(a), "f"(b)); return r;
}
__device__ __forceinline__ void upkf2(uint64_t v, float& a, float& b) {
    asm("mov.b64 {%0, %1}, %2;" : "=f"(a), "=f"(b) : "l"(v));
}
#define MUL2(d, a, b)    asm("mul.rn.f32x2 %0, %1, %2;" : "=l"(d) : "l"(a), "l"(b))
#define FMA2(d, a, b, c) asm("fma.rn.f32x2 %0, %1, %2, %3;" : "=l"(d) : "l"(a), "l"(b), "l"(c))

#define MBAR_INIT(addr, cnt) \
    asm volatile("mbarrier.init.shared.b64 [%0], %1;" :: "r"(addr), "r"(cnt) : "memory")
#define MBAR_ARRIVE(addr) \
    asm volatile("mbarrier.arrive.shared.b64 _, [%0];" :: "r"(addr) : "memory")
#define MBAR_EXPECT_TX(addr, bytes) \
    asm volatile("mbarrier.arrive.expect_tx.shared.b64 _, [%0], %1;" :: "r"(addr), "r"(bytes) : "memory")
#define MBAR_WAIT(addr, parity) do { \
    uint32_t _m = (addr), _p = (parity), _d; \
    asm volatile("{\n\t.reg .pred p;\n\tmbarrier.try_wait.parity.acquire.cta.shared::cta.b64 p, [%1], %2;\n\tselp.b32 %0, 1, 0, p;\n\t}" \
        : "=r"(_d) : "r"(_m), "r"(_p) : "memory"); \
    if (!_d) { \
        asm volatile("{\n\t.reg .pred P1;\n\tWL_%=:\n\tmbarrier.try_wait.parity.acquire.cta.shared::cta.b64 P1, [%0], %1, 0x989680;\n\t@P1 bra.uni WD_%=;\n\tbra.uni WL_%=;\n\tWD_%=:\n\t}" \
            :: "r"(_m), "r"(_p) : "memory"); \
    } \
} while (0)

__device__ __forceinline__ void tma_bulk(uint32_t dst, const void* src, uint32_t bytes, uint32_t mbar) {
    asm volatile("cp.async.bulk.shared::cluster.global.mbarrier::complete_tx::bytes [%0], [%1], %2, [%3];"
                 :: "r"(dst), "l"(src), "r"(bytes), "r"(mbar) : "memory");
}

#define LDSM4(r0, r1, r2, r3, addr) \
    asm volatile("ldmatrix.sync.aligned.m8n8.x4.shared.b16 {%0,%1,%2,%3}, [%4];" \
                 : "=r"(r0), "=r"(r1), "=r"(r2), "=r"(r3) : "r"(addr))

#define MMA_BF(c, a, b0, b1) \
    asm volatile("mma.sync.aligned.m16n8k16.row.col.f32.bf16.bf16.f32 " \
                 "{%0,%1,%2,%3}, {%4,%5,%6,%7}, {%8,%9}, {%0,%1,%2,%3};\n" \
                 : "+f"((c)[0]), "+f"((c)[1]), "+f"((c)[2]), "+f"((c)[3]) \
                 : "r"((a)[0]), "r"((a)[1]), "r"((a)[2]), "r"((a)[3]), "r"(b0), "r"(b1))

#define MMA_FP(c, a, b0, b1) \
    asm volatile("mma.sync.aligned.m16n8k16.row.col.f32.f16.f16.f32 " \
                 "{%0,%1,%2,%3}, {%4,%5,%6,%7}, {%8,%9}, {%0,%1,%2,%3};\n" \
                 : "+f"((c)[0]), "+f"((c)[1]), "+f"((c)[2]), "+f"((c)[3]) \
                 : "r"((a)[0]), "r"((a)[1]), "r"((a)[2]), "r"((a)[3]), "r"(b0), "r"(b1))

// ---------------- mixing ----------------
__global__ void mix_split(const float* __restrict__ x, const float* __restrict__ mask,
                          const float* __restrict__ mr, const float* __restrict__ mw,
                          const float* __restrict__ mk, const float* __restrict__ mv,
                          const float* __restrict__ ma, const float* __restrict__ mg)
{
    size_t p = (size_t)blockIdx.x * blockDim.x + threadIdx.x;
    if (p >= BTC / 2) return;
    int cp = (int)(p % (Cn / 2));
    int c = cp * 2;
    size_t bt = p / (Cn / 2);
    int t = (int)(bt % Tn);
    float m = mask[bt];
    float2 xc = *(const float2*)&x[bt * Cn + c];
    float x0 = xc.x * m, x1 = xc.y * m;
    float p0 = 0.f, p1 = 0.f;
    if (t > 0) {
        float mp = mask[bt - 1];
        float2 xpv = *(const float2*)&x[(bt - 1) * Cn + c];
        p0 = xpv.x * mp; p1 = xpv.y * mp;
    }
    float d0 = p0 - x0, d1 = p1 - x1;
    float2 cr = *(const float2*)&mr[c], cw = *(const float2*)&mw[c];
    float2 ck = *(const float2*)&mk[c], cv = *(const float2*)&mv[c];
    float2 ca = *(const float2*)&ma[c], cg = *(const float2*)&mg[c];

    int mb = (int)(bt >> 7), r = (int)(bt & 127), kt = c >> 5, cc = c & 31;
    size_t ti = tile_idx8(mb, kt, r, cc);
    split_store2(g_xkt, ti, 4096, x0 + d0 * ck.x, x1 + d1 * ck.y);
    split_store2(g_xvt, ti, 4096, x0 + d0 * cv.x, x1 + d1 * cv.y);
    split_store2(g_xwt, ti, 4096, x0 + d0 * cw.x, x1 + d1 * cw.y);
    split_store2(g_xat, ti, 4096, x0 + d0 * ca.x, x1 + d1 * ca.y);
    split_store2(g_xgt, ti, 4096, x0 + d0 * cg.x, x1 + d1 * cg.y);

    size_t ti4 = tile_idx4(mb, kt, r, cc);
    __half2 hr = __floats2half2_rn(x0 + d0 * cr.x, x1 + d1 * cr.y);
    *(uint32_t*)&g_xrt16[ti4] = *(uint32_t*)&hr;
}

// ---------------- weight conversions ----------------
__global__ void conv_wt4(const float* __restrict__ Wr, const float* __restrict__ Wk,
                         const float* __restrict__ Wv, const float* __restrict__ Wo)
{
    size_t p = (size_t)blockIdx.x * blockDim.x + threadIdx.x;
    if (p >= (size_t)Cn * Cn / 2) return;
    int z = blockIdx.y;
    int n = (int)(p / (Cn / 2)), k = (int)(p % (Cn / 2)) * 2;
    if (z == 1 || z == 2) {
        const float* src = (z == 1) ? Wk : Wv;
        float2 v = *(const float2*)&src[(size_t)n * Cn + k];
        split_store2(g_Wt[z - 1], tile_idx8(n >> 7, k >> 5, n & 127, k & 31), 4096, v.x, v.y);
    } else {
        const float* src = (z == 0) ? Wr : Wo;
        __half* dst = (z == 0) ? g_Wr16 : g_Wo16;
        float2 v = *(const float2*)&src[(size_t)n * Cn + k];
        __half2 h = __floats2half2_rn(v.x, v.y);
        *(uint32_t*)&dst[tile_idx4(n >> 7, k >> 5, n & 127, k & 31)] = *(uint32_t*)&h;
    }
}

__global__ void tsplit_all(const float* __restrict__ w1, const float* __restrict__ a1,
                           const float* __restrict__ v1, const float* __restrict__ g1,
                           const float* __restrict__ w2, const float* __restrict__ a2,
                           const float* __restrict__ v2, const float* __restrict__ g2)
{
    int i = blockIdx.x * blockDim.x + threadIdx.x;
    if (i >= KP * Cn) return;
    int z = blockIdx.y;
    if (z < 4) {
        const float* in = (z == 0) ? w1 : (z == 1) ? a1 : (z == 2) ? v1 : g1;
        int nd = (z == 2) ? 64 : (z == 3) ? 128 : 96;
        int n = i / Cn, k = i % Cn;
        float v = (n < nd) ? in[(size_t)k * nd + n] : 0.f;
        split_store(g_w1bt[z], tile_idx8(0, k >> 5, n, k & 31), 4096, v);
    } else {
        int zz = z - 4;
        const float* in = (zz == 0) ? w2 : (zz == 1) ? a2 : (zz == 2) ? v2 : g2;
        int nd = (zz == 2) ? 64 : (zz == 3) ? 128 : 96;
        int n = i / KP, k = i % KP;
        float v = (k < nd) ? in[(size_t)k * Cn + n] : 0.f;
        split_store(g_w2t[zz], (size_t)n * (2 * KP) + k, KP, v);
    }
}

// ---------------- merged bulk-TMA GEMM ----------------
// z 0..1: k/v (bf16 3-term), z 2..5: mlp1 paths (bn==0, bf16 3-term), z 6: r (fp16 single)
__global__ __launch_bounds__(256, 2)
void bgemm3()
{
    const int bn = blockIdx.x, bm = blockIdx.y, z = blockIdx.z;
    if (z >= 2 && z < 6 && bn != 0) return;

    extern __shared__ __align__(1024) char smem[];
    const uint32_t sb = smem_u32(smem);
    const int tid = threadIdx.x, w = tid >> 5, lane = tid & 31;
    const int wm = (w & 3) * 32, wn = (w >> 2) * 64;

    const uint32_t FULL = sb;
    const uint32_t EMPTY = sb + 64;
    const uint32_t ST = sb + 1024;

    if (tid == 0) {
#pragma unroll
        for (int s = 0; s < 3; s++) { MBAR_INIT(FULL + 8 * s, 1); MBAR_INIT(EMPTY + 8 * s, 8); }
    }
    __syncthreads();

    float acc[2][8][4];
#pragma unroll
    for (int mi = 0; mi < 2; mi++)
#pragma unroll
        for (int ni = 0; ni < 8; ni++)
#pragma unroll
            for (int q = 0; q < 4; q++) acc[mi][ni][q] = 0.f;

    if (z == 6) {
        // -------- fp16 single-segment path (r projection) --------
        const __half* A = g_xrt16;
        const __half* Bw = g_Wr16;
        if (tid == 0) {
#pragma unroll
            for (int t = 0; t < 2; t++) {
                MBAR_EXPECT_TX(FULL + 8 * t, 16384u);
                tma_bulk(ST + t * 32768,        A  + ((size_t)(bm * 64 + t)) * 4096, 8192u, FULL + 8 * t);
                tma_bulk(ST + t * 32768 + 8192, Bw + ((size_t)(bn * 64 + t)) * 4096, 8192u, FULL + 8 * t);
            }
        }
        for (int t = 0; t < 64; t++) {
            int s = t % 3;
            if (tid == 0 && t + 2 < 64) {
                int tp = t + 2, sp = tp % 3, up = tp / 3;
                if (up >= 1) MBAR_WAIT(EMPTY + 8 * sp, (up - 1) & 1);
                MBAR_EXPECT_TX(FULL + 8 * sp, 16384u);
                tma_bulk(ST + sp * 32768,        A  + ((size_t)(bm * 64 + tp)) * 4096, 8192u, FULL + 8 * sp);
                tma_bulk(ST + sp * 32768 + 8192, Bw + ((size_t)(bn * 64 + tp)) * 4096, 8192u, FULL + 8 * sp);
            }
            MBAR_WAIT(FULL + 8 * s, (t / 3) & 1);
            const uint32_t st = ST + s * 32768;
#pragma unroll
            for (int kk = 0; kk < 32; kk += 16) {
                uint32_t af[2][4];
#pragma unroll
                for (int mi = 0; mi < 2; mi++) {
                    int rr = wm + mi * 16 + (lane & 15);
                    int c8 = (kk >> 3) + (lane >> 4);
                    int slot = c8 ^ ((rr >> 1) & 3);
                    LDSM4(af[mi][0], af[mi][1], af[mi][2], af[mi][3],
                          st + (uint32_t)(rr * 64 + slot * 16));
                }
#pragma unroll
                for (int n2 = 0; n2 < 4; n2++) {
                    int rb = wn + n2 * 16 + (lane & 7) + ((lane & 16) ? 8 : 0);
                    int c8 = (kk >> 3) + ((lane & 8) ? 1 : 0);
                    int slot = c8 ^ ((rb >> 1) & 3);
                    uint32_t bq[4];
                    LDSM4(bq[0], bq[1], bq[2], bq[3],
                          st + 8192 + (uint32_t)(rb * 64 + slot * 16));
#pragma unroll
                    for (int mi = 0; mi < 2; mi++) {
                        MMA_FP(acc[mi][2 * n2],     af[mi], bq[0], bq[1]);
                        MMA_FP(acc[mi][2 * n2 + 1], af[mi], bq[2], bq[3]);
                    }
                }
            }
            if (lane == 0) MBAR_ARRIVE(EMPTY + 8 * s);
        }
#pragma unroll
        for (int mi = 0; mi < 2; mi++)
#pragma unroll
            for (int ni = 0; ni < 8; ni++) {
                int row = bm * 128 + wm + mi * 16 + (lane >> 2);
                int col = bn * 128 + wn + ni * 8 + (lane & 3) * 2;
                float* c = acc[mi][ni];
                g_r[(size_t)row * Cn + col]           = c[0];
                g_r[(size_t)row * Cn + col + 1]       = c[1];
                g_r[(size_t)(row + 8) * Cn + col]     = c[2];
                g_r[(size_t)(row + 8) * Cn + col + 1] = c[3];
            }
        return;
    }

    // -------- bf16 3-term path --------
    const bf16* A;
    const bf16* Bw;
    if (z < 2) {
        A = (z == 0) ? g_xkt : g_xvt;
        Bw = g_Wt[z];
    } else {
        A = (z == 2) ? g_xwt : (z == 3) ? g_xat : (z == 4) ? g_xvt : g_xgt;
        Bw = g_w1bt[z - 2];
    }

    if (tid == 0) {
#pragma unroll
        for (int t = 0; t < 2; t++) {
            MBAR_EXPECT_TX(FULL + 8 * t, 32768u);
            tma_bulk(ST + t * 32768,         A  + ((size_t)(bm * 64 + t)) * 8192, 16384u, FULL + 8 * t);
            tma_bulk(ST + t * 32768 + 16384, Bw + ((size_t)(bn * 64 + t)) * 8192, 16384u, FULL + 8 * t);
        }
    }

    for (int t = 0; t < 64; t++) {
        int s = t % 3;
        if (tid == 0 && t + 2 < 64) {
            int tp = t + 2, sp = tp % 3, up = tp / 3;
            if (up >= 1) MBAR_WAIT(EMPTY + 8 * sp, (up - 1) & 1);
            MBAR_EXPECT_TX(FULL + 8 * sp, 32768u);
            tma_bulk(ST + sp * 32768,         A  + ((size_t)(bm * 64 + tp)) * 8192, 16384u, FULL + 8 * sp);
            tma_bulk(ST + sp * 32768 + 16384, Bw + ((size_t)(bn * 64 + tp)) * 8192, 16384u, FULL + 8 * sp);
        }
        MBAR_WAIT(FULL + 8 * s, (t / 3) & 1);
        const uint32_t st = ST + s * 32768;

#pragma unroll
        for (int kk = 0; kk < 32; kk += 16) {
            uint32_t ah[2][4], al[2][4];
#pragma unroll
            for (int mi = 0; mi < 2; mi++) {
                int rr = wm + mi * 16 + (lane & 15);
                int c8 = (kk >> 3) + (lane >> 4);
                int slot = c8 ^ ((rr >> 1) & 3);
                uint32_t ad = st + (uint32_t)(rr * 64 + slot * 16);
                LDSM4(ah[mi][0], ah[mi][1], ah[mi][2], ah[mi][3], ad);
                LDSM4(al[mi][0], al[mi][1], al[mi][2], al[mi][3], ad + 8192);
            }
#pragma unroll
            for (int n2 = 0; n2 < 4; n2++) {
                int rb = wn + n2 * 16 + (lane & 7) + ((lane & 16) ? 8 : 0);
                int c8 = (kk >> 3) + ((lane & 8) ? 1 : 0);
                int slot = c8 ^ ((rb >> 1) & 3);
                uint32_t bd = st + 16384 + (uint32_t)(rb * 64 + slot * 16);
                uint32_t bh[4], bl[4];
                LDSM4(bh[0], bh[1], bh[2], bh[3], bd);
                LDSM4(bl[0], bl[1], bl[2], bl[3], bd + 8192);
#pragma unroll
                for (int mi = 0; mi < 2; mi++) {
                    MMA_BF(acc[mi][2 * n2],     ah[mi], bh[0], bh[1]);
                    MMA_BF(acc[mi][2 * n2 + 1], ah[mi], bh[2], bh[3]);
                    MMA_BF(acc[mi][2 * n2],     al[mi], bh[0], bh[1]);
                    MMA_BF(acc[mi][2 * n2 + 1], al[mi], bh[2], bh[3]);
                    MMA_BF(acc[mi][2 * n2],     ah[mi], bl[0], bl[1]);
                    MMA_BF(acc[mi][2 * n2 + 1], ah[mi], bl[2], bl[3]);
                }
            }
        }
        if (lane == 0) MBAR_ARRIVE(EMPTY + 8 * s);
    }

#pragma unroll
    for (int mi = 0; mi < 2; mi++)
#pragma unroll
        for (int ni = 0; ni < 8; ni++) {
            int row = bm * 128 + wm + mi * 16 + (lane >> 2);
            int col = bn * 128 + wn + ni * 8 + (lane & 3) * 2;
            float* c = acc[mi][ni];
            if (z < 2) {
                float* C = (z == 0) ? g_k : g_v;
                C[(size_t)row * Cn + col]           = c[0];
                C[(size_t)row * Cn + col + 1]       = c[1];
                C[(size_t)(row + 8) * Cn + col]     = c[2];
                C[(size_t)(row + 8) * Cn + col + 1] = c[3];
            } else {
                bf16* hid = g_hid4[z - 2];
                auto act = [&](float v) -> float {
                    if (z == 2) return tanhf(v);
                    if (z == 5) return 1.f / (1.f + expf(-v));
                    return v;
                };
                split_store(hid, (size_t)row * 256 + col,           KP, act(c[0]));
                split_store(hid, (size_t)row * 256 + col + 1,       KP, act(c[1]));
                split_store(hid, (size_t)(row + 8) * 256 + col,     KP, act(c[2]));
                split_store(hid, (size_t)(row + 8) * 256 + col + 1, KP, act(c[3]));
            }
        }
}

// ---------------- bulk-TMA fp16 single GEMM (out-proj) ----------------
__global__ __launch_bounds__(256, 2)
void bgemm1(const __half* __restrict__ A, const __half* __restrict__ Bw,
            float* __restrict__ C)
{
    extern __shared__ __align__(1024) char smem[];
    const uint32_t sb = smem_u32(smem);
    const int tid = threadIdx.x, w = tid >> 5, lane = tid & 31;
    const int bn = blockIdx.x, bm = blockIdx.y;
    const int wm = (w & 3) * 32, wn = (w >> 2) * 64;

    const uint32_t FULL = sb;
    const uint32_t EMPTY = sb + 64;
    const uint32_t ST = sb + 1024;

    if (tid == 0) {
#pragma unroll
        for (int s = 0; s < 6; s++) { MBAR_INIT(FULL + 8 * s, 1); MBAR_INIT(EMPTY + 8 * s, 8); }
    }
    __syncthreads();

    if (tid == 0) {
#pragma unroll
        for (int t = 0; t < 5; t++) {
            MBAR_EXPECT_TX(FULL + 8 * t, 16384u);
            tma_bulk(ST + t * 16384,        A  + ((size_t)(bm * 64 + t)) * 4096, 8192u, FULL + 8 * t);
            tma_bulk(ST + t * 16384 + 8192, Bw + ((size_t)(bn * 64 + t)) * 4096, 8192u, FULL + 8 * t);
        }
    }

    float acc[2][8][4];
#pragma unroll
    for (int mi = 0; mi < 2; mi++)
#pragma unroll
        for (int ni = 0; ni < 8; ni++)
#pragma unroll
            for (int q = 0; q < 4; q++) acc[mi][ni][q] = 0.f;

    for (int t = 0; t < 64; t++) {
        int s = t % 6;
        if (tid == 0 && t + 5 < 64) {
            int tp = t + 5, sp = tp % 6, up = tp / 6;
            if (up >= 1) MBAR_WAIT(EMPTY + 8 * sp, (up - 1) & 1);
            MBAR_EXPECT_TX(FULL + 8 * sp, 16384u);
            tma_bulk(ST + sp * 16384,        A  + ((size_t)(bm * 64 + tp)) * 4096, 8192u, FULL + 8 * sp);
            tma_bulk(ST + sp * 16384 + 8192, Bw + ((size_t)(bn * 64 + tp)) * 4096, 8192u, FULL + 8 * sp);
        }
        MBAR_WAIT(FULL + 8 * s, (t / 6) & 1);
        const uint32_t st = ST + s * 16384;

#pragma unroll
        for (int kk = 0; kk < 32; kk += 16) {
            uint32_t af[2][4];
#pragma unroll
            for (int mi = 0; mi < 2; mi++) {
                int rr = wm + mi * 16 + (lane & 15);
                int c8 = (kk >> 3) + (lane >> 4);
                int slot = c8 ^ ((rr >> 1) & 3);
                LDSM4(af[mi][0], af[mi][1], af[mi][2], af[mi][3],
                      st + (uint32_t)(rr * 64 + slot * 16));
            }
#pragma unroll
            for (int n2 = 0; n2 < 4; n2++) {
                int rb = wn + n2 * 16 + (lane & 7) + ((lane & 16) ? 8 : 0);
                int c8 = (kk >> 3) + ((lane & 8) ? 1 : 0);
                int slot = c8 ^ ((rb >> 1) & 3);
                uint32_t bq[4];
                LDSM4(bq[0], bq[1], bq[2], bq[3],
                      st + 8192 + (uint32_t)(rb * 64 + slot * 16));
#pragma unroll
                for (int mi = 0; mi < 2; mi++) {
                    MMA_FP(acc[mi][2 * n2],     af[mi], bq[0], bq[1]);
                    MMA_FP(acc[mi][2 * n2 + 1], af[mi], bq[2], bq[3]);
                }
            }
        }
        if (lane == 0) MBAR_ARRIVE(EMPTY + 8 * s);
    }

#pragma unroll
    for (int mi = 0; mi < 2; mi++)
#pragma unroll
        for (int ni = 0; ni < 8; ni++) {
            int row = bm * 128 + wm + mi * 16 + (lane >> 2);
            int col = bn * 128 + wn + ni * 8 + (lane & 3) * 2;
            float* c = acc[mi][ni];
            C[(size_t)row * Cn + col]           = c[0];
            C[(size_t)row * Cn + col + 1]       = c[1];
            C[(size_t)(row + 8) * Cn + col]     = c[2];
            C[(size_t)(row + 8) * Cn + col + 1] = c[3];
        }
}

// ---------------- mma.sync split-bf16 GEMM for MLP2 ----------------
__global__ __launch_bounds__(256, 2)
void hgemm2(const float* __restrict__ b0, const float* __restrict__ b1,
            const float* __restrict__ b2)
{
    constexpr int TPS = 4;
    constexpr int KT  = 12;
    constexpr int SSZ = 128 * 40;
    extern __shared__ bf16 sh[];
    bf16* As = sh;
    bf16* Bs = sh + 3 * SSZ;

    const int tid = threadIdx.x;
    const int z = blockIdx.z;
    const int bm = blockIdx.y * 128, bn = blockIdx.x * 128;
    const int w = tid >> 5, lane = tid & 31;
    const int wm = (w & 3) * 32, wn = (w >> 2) * 64;

    const bf16* A = g_hid4[z];
    const bf16* Bw = g_w2t[z];

    float acc[2][8][4];
#pragma unroll
    for (int mi = 0; mi < 2; mi++)
#pragma unroll
        for (int ni = 0; ni < 8; ni++)
#pragma unroll
            for (int q = 0; q < 4; q++) acc[mi][ni][q] = 0.f;

    auto loadtile = [&](int stage, int t) {
        int seg = t / TPS, kk = (t % TPS) * 32;
        int aoff = (seg == 1 ? 128 : 0) + kk;
        int boff = (seg == 2 ? 128 : 0) + kk;
        bf16* as = As + stage * SSZ;
        bf16* bs = Bs + stage * SSZ;
#pragma unroll
        for (int c = 0; c < 2; c++) {
            int ch = tid + c * 256;
            int row = ch >> 2, col = ch & 3;
            unsigned sa = (unsigned)__cvta_generic_to_shared(&as[row * 40 + col * 8]);
            const void* ga = &A[(size_t)(bm + row) * 256 + aoff + col * 8];
            asm volatile("cp.async.cg.shared.global [%0], [%1], 16;\n" :: "r"(sa), "l"(ga));
            unsigned sb2 = (unsigned)__cvta_generic_to_shared(&bs[row * 40 + col * 8]);
            const void* gb = &Bw[(size_t)(bn + row) * 256 + boff + col * 8];
            asm volatile("cp.async.cg.shared.global [%0], [%1], 16;\n" :: "r"(sb2), "l"(gb));
        }
        asm volatile("cp.async.commit_group;\n" ::: "memory");
    };

    loadtile(0, 0);
    loadtile(1, 1);

    const int arow = wm + (lane & 15);
    const int acolo = (lane >> 4) << 3;
    const int brow = (lane & 7) + ((lane & 16) ? 8 : 0);
    const int bcolo = (lane & 8) ? 8 : 0;

    for (int t = 0; t < KT; t++) {
        if (t + 1 < KT) {
            asm volatile("cp.async.wait_group 1;\n" ::: "memory");
        } else {
            asm volatile("cp.async.wait_group 0;\n" ::: "memory");
        }
        __syncthreads();
        if (t + 2 < KT) loadtile((t + 2) % 3, t + 2);

        const bf16* as = As + (t % 3) * SSZ;
        const bf16* bs = Bs + (t % 3) * SSZ;
        unsigned abase = (unsigned)__cvta_generic_to_shared(as);
        unsigned bbase = (unsigned)__cvta_generic_to_shared(bs);

#pragma unroll
        for (int kk = 0; kk < 32; kk += 16) {
            uint32_t af[2][4];
#pragma unroll
            for (int mi = 0; mi < 2; mi++) {
                unsigned aaddr = abase + (unsigned)(((arow + mi * 16) * 40 + kk + acolo) * 2);
                LDSM4(af[mi][0], af[mi][1], af[mi][2], af[mi][3], aaddr);
            }
            uint32_t bq[4][4];
#pragma unroll
            for (int n2 = 0; n2 < 4; n2++) {
                unsigned baddr = bbase + (unsigned)(((wn + n2 * 16 + brow) * 40 + kk + bcolo) * 2);
                LDSM4(bq[n2][0], bq[n2][1], bq[n2][2], bq[n2][3], baddr);
            }
#pragma unroll
            for (int n2 = 0; n2 < 4; n2++) {
#pragma unroll
                for (int mi = 0; mi < 2; mi++) {
                    MMA_BF(acc[mi][2 * n2],     af[mi], bq[n2][0], bq[n2][1]);
                    MMA_BF(acc[mi][2 * n2 + 1], af[mi], bq[n2][2], bq[n2][3]);
                }
            }
        }
        __syncthreads();
    }

#pragma unroll
    for (int mi = 0; mi < 2; mi++)
#pragma unroll
        for (int ni = 0; ni < 8; ni++) {
            int row = bm + wm + mi * 16 + (lane >> 2);
            int col = bn + wn + ni * 8 + (lane & 3) * 2;
            float* c = acc[mi][ni];
            float* dst = (z == 0) ? g_wdec : (z == 1) ? g_a : (z == 2) ? g_vg : g_g;
            auto epi = [&](float v, int n) -> float {
                if (z == 0) return expf(-0.60653066f / (1.f + expf(-(b0[n] + v))));
                if (z == 1) return 1.f / (1.f + expf(-(b1[n] + v)));
                if (z == 2) return 1.f / (1.f + expf(-(b2[n] + v)));
                return v;
            };
            dst[(size_t)row * Cn + col]           = epi(c[0], col);
            dst[(size_t)row * Cn + col + 1]       = epi(c[1], col + 1);
            dst[(size_t)(row + 8) * Cn + col]     = epi(c[2], col);
            dst[(size_t)(row + 8) * Cn + col + 1] = epi(c[3], col + 1);
        }
}

// ---------------- fused: v-combine + kk-normalize + k-update ----------------
__global__ __launch_bounds__(256)
void kkv_fused(const float* __restrict__ vf, const float* __restrict__ mask,
               const float* __restrict__ kkw, const float* __restrict__ kaw)
{
    const int warp = threadIdx.x >> 5, lane = threadIdx.x & 31;
    const int gid = blockIdx.x * 8 + warp;
    const int h = gid & (Hn - 1);
    const int bt = gid >> 5;
    size_t base = (size_t)gid * 64;
    int c0 = h * 64 + lane, c1 = c0 + 32;
    float m = mask[bt];

    float v0v = g_v[base + lane], v1v = g_v[base + lane + 32];
    float gt0 = g_vg[base + lane], gt1 = g_vg[base + lane + 32];
    v0v = (v0v + (vf[base + lane] - v0v) * gt0) * m;
    v1v = (v1v + (vf[base + lane + 32] - v1v) * gt1) * m;
    g_v[base + lane] = v0v;
    g_v[base + lane + 32] = v1v;

    float k0v = g_k[base + lane], k1v = g_k[base + lane + 32];
    float kk0 = k0v * kkw[c0], kk1 = k1v * kkw[c1];
    float ss = kk0 * kk0 + kk1 * kk1;
#pragma unroll
    for (int off = 16; off > 0; off >>= 1) ss += __shfl_xor_sync(0xffffffffu, ss, off);
    float inv = 1.f / fmaxf(sqrtf(ss), 1e-12f);
    float a0v = g_a[base + lane], a1v = g_a[base + lane + 32];
    g_nkk[base + lane]      = -kk0 * inv;
    g_nkk[base + lane + 32] = -kk1 * inv;
    g_ab[base + lane]       = kk0 * inv * a0v;
    g_ab[base + lane + 32]  = kk1 * inv * a1v;
    g_knew[base + lane]      = k0v * (1.f + (a0v - 1.f) * kaw[c0]);
    g_knew[base + lane + 32] = k1v * (1.f + (a1v - 1.f) * kaw[c1]);
}

// ---------------- RWKV-7 scan: 256 threads, 4 per state row, packed f32x2 ----------------
__global__ __launch_bounds__(256)
void scan_kernel()
{
    const int bh = blockIdx.x;
    const int b = bh >> 5, h = bh & 31;
    const int tid = threadIdx.x;
    const int j = tid >> 2, q = tid & 3;
    size_t base = (size_t)b * Tn * Cn + h * 64;

    uint64_t S2[8];
    const uint64_t zero2 = pkf2(0.f, 0.f);
#pragma unroll
    for (int i = 0; i < 8; i++) S2[i] = zero2;

    __shared__ float sm[2][384];

    const float* gsrc0;
    const float* gsrc1;
    {
        const float* tbl[6] = {g_r, g_wdec, g_knew, g_v, g_nkk, g_ab};
        int l0 = tid;
        gsrc0 = tbl[l0 >> 6] + base + (l0 & 63);
        int l1 = tid + 256;
        gsrc1 = (tid < 128) ? (tbl[l1 >> 6] + base + (l1 & 63)) : gsrc0;
    }
    float f0 = *gsrc0;
    float f1 = (tid < 128) ? *gsrc1 : 0.f;

    for (int t = 0; t < Tn; t++) {
        float* sb = sm[t & 1];
        sb[tid] = f0;
        if (tid < 128) sb[tid + 256] = f1;
        __syncthreads();

        if (t + 1 < Tn) {
            gsrc0 += Cn;
            f0 = *gsrc0;
            if (tid < 128) { gsrc1 += Cn; f1 = *gsrc1; }
        }

        const uint64_t* rv2 = (const uint64_t*)(sb + q * 16);
        const uint64_t* wv2 = (const uint64_t*)(sb + 64 + q * 16);
        const uint64_t* kv2 = (const uint64_t*)(sb + 128 + q * 16);
        const uint64_t* av2 = (const uint64_t*)(sb + 256 + q * 16);
        const uint64_t* bv2 = (const uint64_t*)(sb + 320 + q * 16);

        uint64_t saA = zero2, saB = zero2;
#pragma unroll
        for (int ii = 0; ii < 8; ii += 2) {
            FMA2(saA, S2[ii],     av2[ii],     saA);
            FMA2(saB, S2[ii + 1], av2[ii + 1], saB);
        }
        float s0, s1, s2, s3;
        upkf2(saA, s0, s1); upkf2(saB, s2, s3);
        float sa = (s0 + s1) + (s2 + s3);
        sa += __shfl_xor_sync(0xffffffffu, sa, 1);
        sa += __shfl_xor_sync(0xffffffffu, sa, 2);

        float vj = sb[192 + j];
        uint64_t vj2 = pkf2(vj, vj);
        uint64_t sa2 = pkf2(sa, sa);
        uint64_t yA = zero2, yB = zero2;
#pragma unroll
        for (int ii = 0; ii < 8; ii += 2) {
            uint64_t t0, t1;
            MUL2(t0, vj2, kv2[ii]);
            MUL2(t1, vj2, kv2[ii + 1]);
            FMA2(t0, sa2, bv2[ii],     t0);
            FMA2(t1, sa2, bv2[ii + 1], t1);
            FMA2(S2[ii],     S2[ii],     wv2[ii],     t0);
            FMA2(S2[ii + 1], S2[ii + 1], wv2[ii + 1], t1);
            FMA2(yA, S2[ii],     rv2[ii],     yA);
            FMA2(yB, S2[ii + 1], rv2[ii + 1], yB);
        }
        float y0, y1, y2, y3;
        upkf2(yA, y0, y1); upkf2(yB, y2, y3);
        float y = (y0 + y1) + (y2 + y3);
        y += __shfl_xor_sync(0xffffffffu, y, 1);
        y += __shfl_xor_sync(0xffffffffu, y, 2);
        if (q == 0) g_y[base + (size_t)t * Cn + j] = y;
    }
}

// ---------------- groupnorm + rk bonus + gate -> fp16 tiled ----------------
__global__ __launch_bounds__(128)
void postln_kernel(const float* __restrict__ rkw, const float* __restrict__ lnw,
                   const float* __restrict__ lnb)
{
    const int warp = threadIdx.x >> 5, lane = threadIdx.x & 31;
    const int gid = blockIdx.x * 4 + warp;
    const int h = gid & (Hn - 1);
    const int bt = gid >> 5;
    size_t base = (size_t)gid * 64;
    int c0 = h * 64 + lane, c1 = c0 + 32;

    float y0 = g_y[base + lane], y1 = g_y[base + lane + 32];
    float s = y0 + y1;
#pragma unroll
    for (int off = 16; off > 0; off >>= 1) s += __shfl_xor_sync(0xffffffffu, s, off);
    float mu = s * (1.f / 64.f);
    float d0 = y0 - mu, d1 = y1 - mu;
    float vs = d0 * d0 + d1 * d1;
#pragma unroll
    for (int off = 16; off > 0; off >>= 1) vs += __shfl_xor_sync(0xffffffffu, vs, off);
    float inv = rsqrtf(vs * (1.f / 64.f) + LN_EPS);

    float rk = g_r[base + lane] * g_knew[base + lane] * rkw[c0]
             + g_r[base + lane + 32] * g_knew[base + lane + 32] * rkw[c1];
#pragma unroll
    for (int off = 16; off > 0; off >>= 1) rk += __shfl_xor_sync(0xffffffffu, rk, off);

    float yn0 = d0 * inv * lnw[c0] + lnb[c0];
    float yn1 = d1 * inv * lnw[c1] + lnb[c1];
    float o0 = (yn0 + rk * g_v[base + lane])      * g_g[base + lane];
    float o1 = (yn1 + rk * g_v[base + lane + 32]) * g_g[base + lane + 32];

    int mb = bt >> 7, r = bt & 127;
    g_ygt[tile_idx4(mb, c0 >> 5, r, c0 & 31)] = __float2half(o0);
    g_ygt[tile_idx4(mb, c1 >> 5, r, c1 & 31)] = __float2half(o1);
}

// ---------------- host ----------------
template<typename T> static T* sym(const void* s) { void* p = nullptr; cudaGetSymbolAddress(&p, s); return (T*)p; }

extern "C" void kernel_launch(void* const* d_in, const int* in_sizes, int n_in,
                              void* d_out, int out_size)
{
    const float* x    = (const float*)d_in[0];
    const float* mask = (const float*)d_in[1];
    const float* vf   = (const float*)d_in[2];
    const float* x_r  = (const float*)d_in[3];
    const float* x_w  = (const float*)d_in[4];
    const float* x_k  = (const float*)d_in[5];
    const float* x_v  = (const float*)d_in[6];
    const float* x_a  = (const float*)d_in[7];
    const float* x_g  = (const float*)d_in[8];
    const float* w0   = (const float*)d_in[9];
    const float* w1   = (const float*)d_in[10];
    const float* w2   = (const float*)d_in[11];
    const float* a0   = (const float*)d_in[12];
    const float* a1   = (const float*)d_in[13];
    const float* a2   = (const float*)d_in[14];
    const float* v0   = (const float*)d_in[15];
    const float* v1   = (const float*)d_in[16];
    const float* v2   = (const float*)d_in[17];
    const float* g1   = (const float*)d_in[18];
    const float* g2   = (const float*)d_in[19];
    const float* k_k  = (const float*)d_in[20];
    const float* k_a  = (const float*)d_in[21];
    const float* r_k  = (const float*)d_in[22];
    const float* W_r  = (const float*)d_in[23];
    const float* W_k  = (const float*)d_in[24];
    const float* W_v  = (const float*)d_in[25];
    const float* W_o  = (const float*)d_in[26];
    const float* ln_w = (const float*)d_in[27];
    const float* ln_b = (const float*)d_in[28];

    __half* p_Wo16  = sym<__half>(g_Wo16);
    __half* p_ygt   = sym<__half>(g_ygt);

    float* out = (float*)d_out;

    const unsigned EW2 = (unsigned)((BTC / 2 + 255) / 256);
    const unsigned WW2 = (unsigned)(((size_t)Cn * Cn / 2 + 255) / 256);
    const unsigned TW = (unsigned)((KP * Cn + 255) / 256);
    const int SHB = 3 * 128 * 40 * 2 * 2;
    const int BSH3 = 1024 + 3 * 32768;
    const int BSH1 = 1024 + 6 * 16384;

    cudaFuncSetAttribute(hgemm2, cudaFuncAttributeMaxDynamicSharedMemorySize, SHB);
    cudaFuncSetAttribute(bgemm3, cudaFuncAttributeMaxDynamicSharedMemorySize, BSH3);
    cudaFuncSetAttribute(bgemm1, cudaFuncAttributeMaxDynamicSharedMemorySize, BSH1);

    // weight prep
    conv_wt4<<<dim3(WW2, 4), 256>>>(W_r, W_k, W_v, W_o);
    tsplit_all<<<dim3(TW, 8), 256>>>(w1, a1, v1, g1, w2, a2, v2, g2);

    // mixing
    mix_split<<<EW2, 256>>>(x, mask, x_r, x_w, x_k, x_v, x_a, x_g);

    // merged: k/v (z0..1) + mlp1 (z2..5) + r fp16 (z6)
    bgemm3<<<dim3(16, 64, 7), 256, BSH3>>>();

    // mlp2 (4 paths)
    hgemm2<<<dim3(16, 64, 4), 256, SHB>>>(w0, a0, v0);

    // fused v-combine + kk
    kkv_fused<<<BT * Hn / 8, 256>>>(vf, mask, k_k, k_a);

    // scan (256 threads, 4 lanes/row)
    scan_kernel<<<Bn * Hn, 256>>>();

    // post groupnorm -> fp16 tiled
    postln_kernel<<<BT * Hn / 4, 128>>>(r_k, ln_w, ln_b);

    // output projection: single fp16
    bgemm1<<<dim3(16, 64), 256, BSH1>>>(p_ygt, p_Wo16, out);

    if ((size_t)out_size >= 2 * BTC) {
        cudaMemcpyAsync(out + BTC, vf, BTC * sizeof(float), cudaMemcpyDeviceToDevice, 0);
    }
}

// round 15
// speedup vs baseline: 1.2377x; 1.2377x over previous
#include <cuda_runtime.h>
#include <cuda_bf16.h>
#include <cuda_fp16.h>
#include <math.h>
#include <stdint.h>

#define Bn 8
#define Tn 1024
#define Cn 2048
#define Hn 32
#define BT (Bn*Tn)                 // 8192
#define BTC ((size_t)BT*Cn)        // 16777216
#define LN_EPS (1e-5f*64.0f)
#define KP 128

typedef __nv_bfloat16 bf16;

// ---------------- scratch ----------------
__device__ float g_r[BTC], g_k[BTC], g_v[BTC], g_wdec[BTC], g_a[BTC], g_vg[BTC];
__device__ float g_g[BTC], g_nkk[BTC], g_ab[BTC], g_knew[BTC], g_y[BTC];
__device__ __align__(128) bf16 g_xkt[(size_t)BT*4096], g_xvt[(size_t)BT*4096];
__device__ __align__(128) bf16 g_xwt[(size_t)BT*4096], g_xat[(size_t)BT*4096], g_xgt[(size_t)BT*4096];
__device__ __align__(128) __half g_xrt16[(size_t)BT*2048];
__device__ __align__(128) __half g_ygt[(size_t)BT*2048];
__device__ __align__(128) bf16 g_Wt[2][(size_t)Cn*4096];          // Wk, Wv
__device__ __align__(128) __half g_Wr16[(size_t)Cn*2048];
__device__ __align__(128) __half g_Wo16[(size_t)Cn*2048];
__device__ __align__(128) bf16 g_w1bt[4][(size_t)64*8192];
__device__ __align__(128) bf16 g_w2t[4][(size_t)Cn*2*KP];
__device__ __align__(128) bf16 g_hid4[4][(size_t)BT*256];

// ---------------- helpers ----------------
__device__ __forceinline__ void split_store(bf16* dst, size_t hi_idx, size_t lo_off, float v) {
    bf16 hi = __float2bfloat16(v);
    bf16 lo = __float2bfloat16(v - __bfloat162float(hi));
    dst[hi_idx] = hi;
    dst[hi_idx + lo_off] = lo;
}

__device__ __forceinline__ uint32_t pack2(bf16 a, bf16 b) {
    return ((uint32_t)*(uint16_t*)&b << 16) | (uint32_t)*(uint16_t*)&a;
}

__device__ __forceinline__ void split_store2(bf16* dst, size_t hi_idx, size_t lo_off,
                                             float v0, float v1) {
    bf16 h0 = __float2bfloat16(v0), h1 = __float2bfloat16(v1);
    bf16 l0 = __float2bfloat16(v0 - __bfloat162float(h0));
    bf16 l1 = __float2bfloat16(v1 - __bfloat162float(h1));
    *(uint32_t*)&dst[hi_idx] = pack2(h0, h1);
    *(uint32_t*)&dst[hi_idx + lo_off] = pack2(l0, l1);
}

__device__ __forceinline__ size_t tile_idx8(int mb, int kt, int r, int cc) {
    int slot = (cc >> 3) ^ ((r >> 1) & 3);
    return ((size_t)(mb * 64 + kt)) * 8192 + r * 32 + slot * 8 + (cc & 7);
}
__device__ __forceinline__ size_t tile_idx4(int mb, int kt, int r, int cc) {
    int slot = (cc >> 3) ^ ((r >> 1) & 3);
    return ((size_t)(mb * 64 + kt)) * 4096 + r * 32 + slot * 8 + (cc & 7);
}

__device__ __forceinline__ uint32_t smem_u32(const void* p) {
    return (uint32_t)__cvta_generic_to_shared(p);
}

__device__ __forceinline__ uint64_t pkf2(float a, float b) {
    uint64_t r; asm("mov.b64 %0, {%1, %2};" : "=l"(r) : "f"(a), "f"(b)); return r;
}
__device__ __forceinline__ void upkf2(uint64_t v, float& a, float& b) {
    asm("mov.b64 {%0, %1}, %2;" : "=f"(a), "=f"(b) : "l"(v));
}
#define MUL2(d, a, b)    asm("mul.rn.f32x2 %0, %1, %2;" : "=l"(d) : "l"(a), "l"(b))
#define FMA2(d, a, b, c) asm("fma.rn.f32x2 %0, %1, %2, %3;" : "=l"(d) : "l"(a), "l"(b), "l"(c))

#define MBAR_INIT(addr, cnt) \
    asm volatile("mbarrier.init.shared.b64 [%0], %1;" :: "r"(addr), "r"(cnt) : "memory")
#define MBAR_ARRIVE(addr) \
    asm volatile("mbarrier.arrive.shared.b64 _, [%0];" :: "r"(addr) : "memory")
#define MBAR_EXPECT_TX(addr, bytes) \
    asm volatile("mbarrier.arrive.expect_tx.shared.b64 _, [%0], %1;" :: "r"(addr), "r"(bytes) : "memory")
#define MBAR_WAIT(addr, parity) do { \
    uint32_t _m = (addr), _p = (parity), _d; \
    asm volatile("{\n\t.reg .pred p;\n\tmbarrier.try_wait.parity.acquire.cta.shared::cta.b64 p, [%1], %2;\n\tselp.b32 %0, 1, 0, p;\n\t}" \
        : "=r"(_d) : "r"(_m), "r"(_p) : "memory"); \
    if (!_d) { \
        asm volatile("{\n\t.reg .pred P1;\n\tWL_%=:\n\tmbarrier.try_wait.parity.acquire.cta.shared::cta.b64 P1, [%0], %1, 0x989680;\n\t@P1 bra.uni WD_%=;\n\tbra.uni WL_%=;\n\tWD_%=:\n\t}" \
            :: "r"(_m), "r"(_p) : "memory"); \
    } \
} while (0)

__device__ __forceinline__ void tma_bulk(uint32_t dst, const void* src, uint32_t bytes, uint32_t mbar) {
    asm volatile("cp.async.bulk.shared::cluster.global.mbarrier::complete_tx::bytes [%0], [%1], %2, [%3];"
                 :: "r"(dst), "l"(src), "r"(bytes), "r"(mbar) : "memory");
}

#define LDSM4(r0, r1, r2, r3, addr) \
    asm volatile("ldmatrix.sync.aligned.m8n8.x4.shared.b16 {%0,%1,%2,%3}, [%4];" \
                 : "=r"(r0), "=r"(r1), "=r"(r2), "=r"(r3) : "r"(addr))

#define MMA_BF(c, a, b0, b1) \
    asm volatile("mma.sync.aligned.m16n8k16.row.col.f32.bf16.bf16.f32 " \
                 "{%0,%1,%2,%3}, {%4,%5,%6,%7}, {%8,%9}, {%0,%1,%2,%3};\n" \
                 : "+f"((c)[0]), "+f"((c)[1]), "+f"((c)[2]), "+f"((c)[3]) \
                 : "r"((a)[0]), "r"((a)[1]), "r"((a)[2]), "r"((a)[3]), "r"(b0), "r"(b1))

#define MMA_FP(c, a, b0, b1) \
    asm volatile("mma.sync.aligned.m16n8k16.row.col.f32.f16.f16.f32 " \
                 "{%0,%1,%2,%3}, {%4,%5,%6,%7}, {%8,%9}, {%0,%1,%2,%3};\n" \
                 : "+f"((c)[0]), "+f"((c)[1]), "+f"((c)[2]), "+f"((c)[3]) \
                 : "r"((a)[0]), "r"((a)[1]), "r"((a)[2]), "r"((a)[3]), "r"(b0), "r"(b1))

// ---------------- mixing ----------------
__global__ void mix_split(const float* __restrict__ x, const float* __restrict__ mask,
                          const float* __restrict__ mr, const float* __restrict__ mw,
                          const float* __restrict__ mk, const float* __restrict__ mv,
                          const float* __restrict__ ma, const float* __restrict__ mg)
{
    size_t p = (size_t)blockIdx.x * blockDim.x + threadIdx.x;
    if (p >= BTC / 2) return;
    int cp = (int)(p % (Cn / 2));
    int c = cp * 2;
    size_t bt = p / (Cn / 2);
    int t = (int)(bt % Tn);
    float m = mask[bt];
    float2 xc = *(const float2*)&x[bt * Cn + c];
    float x0 = xc.x * m, x1 = xc.y * m;
    float p0 = 0.f, p1 = 0.f;
    if (t > 0) {
        float mp = mask[bt - 1];
        float2 xpv = *(const float2*)&x[(bt - 1) * Cn + c];
        p0 = xpv.x * mp; p1 = xpv.y * mp;
    }
    float d0 = p0 - x0, d1 = p1 - x1;
    float2 cr = *(const float2*)&mr[c], cw = *(const float2*)&mw[c];
    float2 ck = *(const float2*)&mk[c], cv = *(const float2*)&mv[c];
    float2 ca = *(const float2*)&ma[c], cg = *(const float2*)&mg[c];

    int mb = (int)(bt >> 7), r = (int)(bt & 127), kt = c >> 5, cc = c & 31;
    size_t ti = tile_idx8(mb, kt, r, cc);
    split_store2(g_xkt, ti, 4096, x0 + d0 * ck.x, x1 + d1 * ck.y);
    split_store2(g_xvt, ti, 4096, x0 + d0 * cv.x, x1 + d1 * cv.y);
    split_store2(g_xwt, ti, 4096, x0 + d0 * cw.x, x1 + d1 * cw.y);
    split_store2(g_xat, ti, 4096, x0 + d0 * ca.x, x1 + d1 * ca.y);
    split_store2(g_xgt, ti, 4096, x0 + d0 * cg.x, x1 + d1 * cg.y);

    size_t ti4 = tile_idx4(mb, kt, r, cc);
    __half2 hr = __floats2half2_rn(x0 + d0 * cr.x, x1 + d1 * cr.y);
    *(uint32_t*)&g_xrt16[ti4] = *(uint32_t*)&hr;
}

// ---------------- weight conversions ----------------
__global__ void conv_wt4(const float* __restrict__ Wr, const float* __restrict__ Wk,
                         const float* __restrict__ Wv, const float* __restrict__ Wo)
{
    size_t p = (size_t)blockIdx.x * blockDim.x + threadIdx.x;
    if (p >= (size_t)Cn * Cn / 2) return;
    int z = blockIdx.y;
    int n = (int)(p / (Cn / 2)), k = (int)(p % (Cn / 2)) * 2;
    if (z == 1 || z == 2) {
        const float* src = (z == 1) ? Wk : Wv;
        float2 v = *(const float2*)&src[(size_t)n * Cn + k];
        split_store2(g_Wt[z - 1], tile_idx8(n >> 7, k >> 5, n & 127, k & 31), 4096, v.x, v.y);
    } else {
        const float* src = (z == 0) ? Wr : Wo;
        __half* dst = (z == 0) ? g_Wr16 : g_Wo16;
        float2 v = *(const float2*)&src[(size_t)n * Cn + k];
        __half2 h = __floats2half2_rn(v.x, v.y);
        *(uint32_t*)&dst[tile_idx4(n >> 7, k >> 5, n & 127, k & 31)] = *(uint32_t*)&h;
    }
}

__global__ void tsplit_all(const float* __restrict__ w1, const float* __restrict__ a1,
                           const float* __restrict__ v1, const float* __restrict__ g1,
                           const float* __restrict__ w2, const float* __restrict__ a2,
                           const float* __restrict__ v2, const float* __restrict__ g2)
{
    int i = blockIdx.x * blockDim.x + threadIdx.x;
    if (i >= KP * Cn) return;
    int z = blockIdx.y;
    if (z < 4) {
        const float* in = (z == 0) ? w1 : (z == 1) ? a1 : (z == 2) ? v1 : g1;
        int nd = (z == 2) ? 64 : (z == 3) ? 128 : 96;
        int n = i / Cn, k = i % Cn;
        float v = (n < nd) ? in[(size_t)k * nd + n] : 0.f;
        split_store(g_w1bt[z], tile_idx8(0, k >> 5, n, k & 31), 4096, v);
    } else {
        int zz = z - 4;
        const float* in = (zz == 0) ? w2 : (zz == 1) ? a2 : (zz == 2) ? v2 : g2;
        int nd = (zz == 2) ? 64 : (zz == 3) ? 128 : 96;
        int n = i / KP, k = i % KP;
        float v = (k < nd) ? in[(size_t)k * Cn + n] : 0.f;
        split_store(g_w2t[zz], (size_t)n * (2 * KP) + k, KP, v);
    }
}

// ---------------- merged bulk-TMA GEMM ----------------
// z 0..1: k/v (bf16 3-term, 3 stages x 32KB); z 2..5: mlp1 (bn==0, bf16 3-term);
// z 6: r (fp16 single-segment, 6 stages x 16KB — same pipeline as bgemm1)
__global__ __launch_bounds__(256, 2)
void bgemm3()
{
    const int bn = blockIdx.x, bm = blockIdx.y, z = blockIdx.z;
    if (z >= 2 && z < 6 && bn != 0) return;

    extern __shared__ __align__(1024) char smem[];
    const uint32_t sb = smem_u32(smem);
    const int tid = threadIdx.x, w = tid >> 5, lane = tid & 31;
    const int wm = (w & 3) * 32, wn = (w >> 2) * 64;

    const uint32_t FULL = sb;
    const uint32_t EMPTY = sb + 64;
    const uint32_t ST = sb + 1024;

    if (tid == 0) {
#pragma unroll
        for (int s = 0; s < 6; s++) { MBAR_INIT(FULL + 8 * s, 1); MBAR_INIT(EMPTY + 8 * s, 8); }
    }
    __syncthreads();

    float acc[2][8][4];
#pragma unroll
    for (int mi = 0; mi < 2; mi++)
#pragma unroll
        for (int ni = 0; ni < 8; ni++)
#pragma unroll
            for (int q = 0; q < 4; q++) acc[mi][ni][q] = 0.f;

    if (z == 6) {
        // -------- fp16 single-segment (r projection), 6-stage 16KB pipeline --------
        const __half* A = g_xrt16;
        const __half* Bw = g_Wr16;
        if (tid == 0) {
#pragma unroll
            for (int t = 0; t < 5; t++) {
                MBAR_EXPECT_TX(FULL + 8 * t, 16384u);
                tma_bulk(ST + t * 16384,        A  + ((size_t)(bm * 64 + t)) * 4096, 8192u, FULL + 8 * t);
                tma_bulk(ST + t * 16384 + 8192, Bw + ((size_t)(bn * 64 + t)) * 4096, 8192u, FULL + 8 * t);
            }
        }
        for (int t = 0; t < 64; t++) {
            int s = t % 6;
            if (tid == 0 && t + 5 < 64) {
                int tp = t + 5, sp = tp % 6, up = tp / 6;
                if (up >= 1) MBAR_WAIT(EMPTY + 8 * sp, (up - 1) & 1);
                MBAR_EXPECT_TX(FULL + 8 * sp, 16384u);
                tma_bulk(ST + sp * 16384,        A  + ((size_t)(bm * 64 + tp)) * 4096, 8192u, FULL + 8 * sp);
                tma_bulk(ST + sp * 16384 + 8192, Bw + ((size_t)(bn * 64 + tp)) * 4096, 8192u, FULL + 8 * sp);
            }
            MBAR_WAIT(FULL + 8 * s, (t / 6) & 1);
            const uint32_t st = ST + s * 16384;
#pragma unroll
            for (int kk = 0; kk < 32; kk += 16) {
                uint32_t af[2][4];
#pragma unroll
                for (int mi = 0; mi < 2; mi++) {
                    int rr = wm + mi * 16 + (lane & 15);
                    int c8 = (kk >> 3) + (lane >> 4);
                    int slot = c8 ^ ((rr >> 1) & 3);
                    LDSM4(af[mi][0], af[mi][1], af[mi][2], af[mi][3],
                          st + (uint32_t)(rr * 64 + slot * 16));
                }
#pragma unroll
                for (int n2 = 0; n2 < 4; n2++) {
                    int rb = wn + n2 * 16 + (lane & 7) + ((lane & 16) ? 8 : 0);
                    int c8 = (kk >> 3) + ((lane & 8) ? 1 : 0);
                    int slot = c8 ^ ((rb >> 1) & 3);
                    uint32_t bq[4];
                    LDSM4(bq[0], bq[1], bq[2], bq[3],
                          st + 8192 + (uint32_t)(rb * 64 + slot * 16));
#pragma unroll
                    for (int mi = 0; mi < 2; mi++) {
                        MMA_FP(acc[mi][2 * n2],     af[mi], bq[0], bq[1]);
                        MMA_FP(acc[mi][2 * n2 + 1], af[mi], bq[2], bq[3]);
                    }
                }
            }
            if (lane == 0) MBAR_ARRIVE(EMPTY + 8 * s);
        }
#pragma unroll
        for (int mi = 0; mi < 2; mi++)
#pragma unroll
            for (int ni = 0; ni < 8; ni++) {
                int row = bm * 128 + wm + mi * 16 + (lane >> 2);
                int col = bn * 128 + wn + ni * 8 + (lane & 3) * 2;
                float* c = acc[mi][ni];
                g_r[(size_t)row * Cn + col]           = c[0];
                g_r[(size_t)row * Cn + col + 1]       = c[1];
                g_r[(size_t)(row + 8) * Cn + col]     = c[2];
                g_r[(size_t)(row + 8) * Cn + col + 1] = c[3];
            }
        return;
    }

    // -------- bf16 3-term path (3 stages x 32KB) --------
    const bf16* A;
    const bf16* Bw;
    if (z < 2) {
        A = (z == 0) ? g_xkt : g_xvt;
        Bw = g_Wt[z];
    } else {
        A = (z == 2) ? g_xwt : (z == 3) ? g_xat : (z == 4) ? g_xvt : g_xgt;
        Bw = g_w1bt[z - 2];
    }

    if (tid == 0) {
#pragma unroll
        for (int t = 0; t < 2; t++) {
            MBAR_EXPECT_TX(FULL + 8 * t, 32768u);
            tma_bulk(ST + t * 32768,         A  + ((size_t)(bm * 64 + t)) * 8192, 16384u, FULL + 8 * t);
            tma_bulk(ST + t * 32768 + 16384, Bw + ((size_t)(bn * 64 + t)) * 8192, 16384u, FULL + 8 * t);
        }
    }

    for (int t = 0; t < 64; t++) {
        int s = t % 3;
        if (tid == 0 && t + 2 < 64) {
            int tp = t + 2, sp = tp % 3, up = tp / 3;
            if (up >= 1) MBAR_WAIT(EMPTY + 8 * sp, (up - 1) & 1);
            MBAR_EXPECT_TX(FULL + 8 * sp, 32768u);
            tma_bulk(ST + sp * 32768,         A  + ((size_t)(bm * 64 + tp)) * 8192, 16384u, FULL + 8 * sp);
            tma_bulk(ST + sp * 32768 + 16384, Bw + ((size_t)(bn * 64 + tp)) * 8192, 16384u, FULL + 8 * sp);
        }
        MBAR_WAIT(FULL + 8 * s, (t / 3) & 1);
        const uint32_t st = ST + s * 32768;

#pragma unroll
        for (int kk = 0; kk < 32; kk += 16) {
            uint32_t ah[2][4], al[2][4];
#pragma unroll
            for (int mi = 0; mi < 2; mi++) {
                int rr = wm + mi * 16 + (lane & 15);
                int c8 = (kk >> 3) + (lane >> 4);
                int slot = c8 ^ ((rr >> 1) & 3);
                uint32_t ad = st + (uint32_t)(rr * 64 + slot * 16);
                LDSM4(ah[mi][0], ah[mi][1], ah[mi][2], ah[mi][3], ad);
                LDSM4(al[mi][0], al[mi][1], al[mi][2], al[mi][3], ad + 8192);
            }
#pragma unroll
            for (int n2 = 0; n2 < 4; n2++) {
                int rb = wn + n2 * 16 + (lane & 7) + ((lane & 16) ? 8 : 0);
                int c8 = (kk >> 3) + ((lane & 8) ? 1 : 0);
                int slot = c8 ^ ((rb >> 1) & 3);
                uint32_t bd = st + 16384 + (uint32_t)(rb * 64 + slot * 16);
                uint32_t bh[4], bl[4];
                LDSM4(bh[0], bh[1], bh[2], bh[3], bd);
                LDSM4(bl[0], bl[1], bl[2], bl[3], bd + 8192);
#pragma unroll
                for (int mi = 0; mi < 2; mi++) {
                    MMA_BF(acc[mi][2 * n2],     ah[mi], bh[0], bh[1]);
                    MMA_BF(acc[mi][2 * n2 + 1], ah[mi], bh[2], bh[3]);
                    MMA_BF(acc[mi][2 * n2],     al[mi], bh[0], bh[1]);
                    MMA_BF(acc[mi][2 * n2 + 1], al[mi], bh[2], bh[3]);
                    MMA_BF(acc[mi][2 * n2],     ah[mi], bl[0], bl[1]);
                    MMA_BF(acc[mi][2 * n2 + 1], ah[mi], bl[2], bl[3]);
                }
            }
        }
        if (lane == 0) MBAR_ARRIVE(EMPTY + 8 * s);
    }

#pragma unroll
    for (int mi = 0; mi < 2; mi++)
#pragma unroll
        for (int ni = 0; ni < 8; ni++) {
            int row = bm * 128 + wm + mi * 16 + (lane >> 2);
            int col = bn * 128 + wn + ni * 8 + (lane & 3) * 2;
            float* c = acc[mi][ni];
            if (z < 2) {
                float* C = (z == 0) ? g_k : g_v;
                C[(size_t)row * Cn + col]           = c[0];
                C[(size_t)row * Cn + col + 1]       = c[1];
                C[(size_t)(row + 8) * Cn + col]     = c[2];
                C[(size_t)(row + 8) * Cn + col + 1] = c[3];
            } else {
                bf16* hid = g_hid4[z - 2];
                auto act = [&](float v) -> float {
                    if (z == 2) return tanhf(v);
                    if (z == 5) return 1.f / (1.f + expf(-v));
                    return v;
                };
                split_store(hid, (size_t)row * 256 + col,           KP, act(c[0]));
                split_store(hid, (size_t)row * 256 + col + 1,       KP, act(c[1]));
                split_store(hid, (size_t)(row + 8) * 256 + col,     KP, act(c[2]));
                split_store(hid, (size_t)(row + 8) * 256 + col + 1, KP, act(c[3]));
            }
        }
}

// ---------------- bulk-TMA fp16 single GEMM (out-proj) ----------------
__global__ __launch_bounds__(256, 2)
void bgemm1(const __half* __restrict__ A, const __half* __restrict__ Bw,
            float* __restrict__ C)
{
    extern __shared__ __align__(1024) char smem[];
    const uint32_t sb = smem_u32(smem);
    const int tid = threadIdx.x, w = tid >> 5, lane = tid & 31;
    const int bn = blockIdx.x, bm = blockIdx.y;
    const int wm = (w & 3) * 32, wn = (w >> 2) * 64;

    const uint32_t FULL = sb;
    const uint32_t EMPTY = sb + 64;
    const uint32_t ST = sb + 1024;

    if (tid == 0) {
#pragma unroll
        for (int s = 0; s < 6; s++) { MBAR_INIT(FULL + 8 * s, 1); MBAR_INIT(EMPTY + 8 * s, 8); }
    }
    __syncthreads();

    if (tid == 0) {
#pragma unroll
        for (int t = 0; t < 5; t++) {
            MBAR_EXPECT_TX(FULL + 8 * t, 16384u);
            tma_bulk(ST + t * 16384,        A  + ((size_t)(bm * 64 + t)) * 4096, 8192u, FULL + 8 * t);
            tma_bulk(ST + t * 16384 + 8192, Bw + ((size_t)(bn * 64 + t)) * 4096, 8192u, FULL + 8 * t);
        }
    }

    float acc[2][8][4];
#pragma unroll
    for (int mi = 0; mi < 2; mi++)
#pragma unroll
        for (int ni = 0; ni < 8; ni++)
#pragma unroll
            for (int q = 0; q < 4; q++) acc[mi][ni][q] = 0.f;

    for (int t = 0; t < 64; t++) {
        int s = t % 6;
        if (tid == 0 && t + 5 < 64) {
            int tp = t + 5, sp = tp % 6, up = tp / 6;
            if (up >= 1) MBAR_WAIT(EMPTY + 8 * sp, (up - 1) & 1);
            MBAR_EXPECT_TX(FULL + 8 * sp, 16384u);
            tma_bulk(ST + sp * 16384,        A  + ((size_t)(bm * 64 + tp)) * 4096, 8192u, FULL + 8 * sp);
            tma_bulk(ST + sp * 16384 + 8192, Bw + ((size_t)(bn * 64 + tp)) * 4096, 8192u, FULL + 8 * sp);
        }
        MBAR_WAIT(FULL + 8 * s, (t / 6) & 1);
        const uint32_t st = ST + s * 16384;

#pragma unroll
        for (int kk = 0; kk < 32; kk += 16) {
            uint32_t af[2][4];
#pragma unroll
            for (int mi = 0; mi < 2; mi++) {
                int rr = wm + mi * 16 + (lane & 15);
                int c8 = (kk >> 3) + (lane >> 4);
                int slot = c8 ^ ((rr >> 1) & 3);
                LDSM4(af[mi][0], af[mi][1], af[mi][2], af[mi][3],
                      st + (uint32_t)(rr * 64 + slot * 16));
            }
#pragma unroll
            for (int n2 = 0; n2 < 4; n2++) {
                int rb = wn + n2 * 16 + (lane & 7) + ((lane & 16) ? 8 : 0);
                int c8 = (kk >> 3) + ((lane & 8) ? 1 : 0);
                int slot = c8 ^ ((rb >> 1) & 3);
                uint32_t bq[4];
                LDSM4(bq[0], bq[1], bq[2], bq[3],
                      st + 8192 + (uint32_t)(rb * 64 + slot * 16));
#pragma unroll
                for (int mi = 0; mi < 2; mi++) {
                    MMA_FP(acc[mi][2 * n2],     af[mi], bq[0], bq[1]);
                    MMA_FP(acc[mi][2 * n2 + 1], af[mi], bq[2], bq[3]);
                }
            }
        }
        if (lane == 0) MBAR_ARRIVE(EMPTY + 8 * s);
    }

#pragma unroll
    for (int mi = 0; mi < 2; mi++)
#pragma unroll
        for (int ni = 0; ni < 8; ni++) {
            int row = bm * 128 + wm + mi * 16 + (lane >> 2);
            int col = bn * 128 + wn + ni * 8 + (lane & 3) * 2;
            float* c = acc[mi][ni];
            C[(size_t)row * Cn + col]           = c[0];
            C[(size_t)row * Cn + col + 1]       = c[1];
            C[(size_t)(row + 8) * Cn + col]     = c[2];
            C[(size_t)(row + 8) * Cn + col + 1] = c[3];
        }
}

// ---------------- mma.sync split-bf16 GEMM for MLP2 ----------------
__global__ __launch_bounds__(256, 2)
void hgemm2(const float* __restrict__ b0, const float* __restrict__ b1,
            const float* __restrict__ b2)
{
    constexpr int TPS = 4;
    constexpr int KT  = 12;
    constexpr int SSZ = 128 * 40;
    extern __shared__ bf16 sh[];
    bf16* As = sh;
    bf16* Bs = sh + 3 * SSZ;

    const int tid = threadIdx.x;
    const int z = blockIdx.z;
    const int bm = blockIdx.y * 128, bn = blockIdx.x * 128;
    const int w = tid >> 5, lane = tid & 31;
    const int wm = (w & 3) * 32, wn = (w >> 2) * 64;

    const bf16* A = g_hid4[z];
    const bf16* Bw = g_w2t[z];

    float acc[2][8][4];
#pragma unroll
    for (int mi = 0; mi < 2; mi++)
#pragma unroll
        for (int ni = 0; ni < 8; ni++)
#pragma unroll
            for (int q = 0; q < 4; q++) acc[mi][ni][q] = 0.f;

    auto loadtile = [&](int stage, int t) {
        int seg = t / TPS, kk = (t % TPS) * 32;
        int aoff = (seg == 1 ? 128 : 0) + kk;
        int boff = (seg == 2 ? 128 : 0) + kk;
        bf16* as = As + stage * SSZ;
        bf16* bs = Bs + stage * SSZ;
#pragma unroll
        for (int c = 0; c < 2; c++) {
            int ch = tid + c * 256;
            int row = ch >> 2, col = ch & 3;
            unsigned sa = (unsigned)__cvta_generic_to_shared(&as[row * 40 + col * 8]);
            const void* ga = &A[(size_t)(bm + row) * 256 + aoff + col * 8];
            asm volatile("cp.async.cg.shared.global [%0], [%1], 16;\n" :: "r"(sa), "l"(ga));
            unsigned sb2 = (unsigned)__cvta_generic_to_shared(&bs[row * 40 + col * 8]);
            const void* gb = &Bw[(size_t)(bn + row) * 256 + boff + col * 8];
            asm volatile("cp.async.cg.shared.global [%0], [%1], 16;\n" :: "r"(sb2), "l"(gb));
        }
        asm volatile("cp.async.commit_group;\n" ::: "memory");
    };

    loadtile(0, 0);
    loadtile(1, 1);

    const int arow = wm + (lane & 15);
    const int acolo = (lane >> 4) << 3;
    const int brow = (lane & 7) + ((lane & 16) ? 8 : 0);
    const int bcolo = (lane & 8) ? 8 : 0;

    for (int t = 0; t < KT; t++) {
        if (t + 1 < KT) {
            asm volatile("cp.async.wait_group 1;\n" ::: "memory");
        } else {
            asm volatile("cp.async.wait_group 0;\n" ::: "memory");
        }
        __syncthreads();
        if (t + 2 < KT) loadtile((t + 2) % 3, t + 2);

        const bf16* as = As + (t % 3) * SSZ;
        const bf16* bs = Bs + (t % 3) * SSZ;
        unsigned abase = (unsigned)__cvta_generic_to_shared(as);
        unsigned bbase = (unsigned)__cvta_generic_to_shared(bs);

#pragma unroll
        for (int kk = 0; kk < 32; kk += 16) {
            uint32_t af[2][4];
#pragma unroll
            for (int mi = 0; mi < 2; mi++) {
                unsigned aaddr = abase + (unsigned)(((arow + mi * 16) * 40 + kk + acolo) * 2);
                LDSM4(af[mi][0], af[mi][1], af[mi][2], af[mi][3], aaddr);
            }
            uint32_t bq[4][4];
#pragma unroll
            for (int n2 = 0; n2 < 4; n2++) {
                unsigned baddr = bbase + (unsigned)(((wn + n2 * 16 + brow) * 40 + kk + bcolo) * 2);
                LDSM4(bq[n2][0], bq[n2][1], bq[n2][2], bq[n2][3], baddr);
            }
#pragma unroll
            for (int n2 = 0; n2 < 4; n2++) {
#pragma unroll
                for (int mi = 0; mi < 2; mi++) {
                    MMA_BF(acc[mi][2 * n2],     af[mi], bq[n2][0], bq[n2][1]);
                    MMA_BF(acc[mi][2 * n2 + 1], af[mi], bq[n2][2], bq[n2][3]);
                }
            }
        }
        __syncthreads();
    }

#pragma unroll
    for (int mi = 0; mi < 2; mi++)
#pragma unroll
        for (int ni = 0; ni < 8; ni++) {
            int row = bm + wm + mi * 16 + (lane >> 2);
            int col = bn + wn + ni * 8 + (lane & 3) * 2;
            float* c = acc[mi][ni];
            float* dst = (z == 0) ? g_wdec : (z == 1) ? g_a : (z == 2) ? g_vg : g_g;
            auto epi = [&](float v, int n) -> float {
                if (z == 0) return expf(-0.60653066f / (1.f + expf(-(b0[n] + v))));
                if (z == 1) return 1.f / (1.f + expf(-(b1[n] + v)));
                if (z == 2) return 1.f / (1.f + expf(-(b2[n] + v)));
                return v;
            };
            dst[(size_t)row * Cn + col]           = epi(c[0], col);
            dst[(size_t)row * Cn + col + 1]       = epi(c[1], col + 1);
            dst[(size_t)(row + 8) * Cn + col]     = epi(c[2], col);
            dst[(size_t)(row + 8) * Cn + col + 1] = epi(c[3], col + 1);
        }
}

// ---------------- fused: v-combine + kk-normalize + k-update ----------------
__global__ __launch_bounds__(256)
void kkv_fused(const float* __restrict__ vf, const float* __restrict__ mask,
               const float* __restrict__ kkw, const float* __restrict__ kaw)
{
    const int warp = threadIdx.x >> 5, lane = threadIdx.x & 31;
    const int gid = blockIdx.x * 8 + warp;
    const int h = gid & (Hn - 1);
    const int bt = gid >> 5;
    size_t base = (size_t)gid * 64;
    int c0 = h * 64 + lane, c1 = c0 + 32;
    float m = mask[bt];

    float v0v = g_v[base + lane], v1v = g_v[base + lane + 32];
    float gt0 = g_vg[base + lane], gt1 = g_vg[base + lane + 32];
    v0v = (v0v + (vf[base + lane] - v0v) * gt0) * m;
    v1v = (v1v + (vf[base + lane + 32] - v1v) * gt1) * m;
    g_v[base + lane] = v0v;
    g_v[base + lane + 32] = v1v;

    float k0v = g_k[base + lane], k1v = g_k[base + lane + 32];
    float kk0 = k0v * kkw[c0], kk1 = k1v * kkw[c1];
    float ss = kk0 * kk0 + kk1 * kk1;
#pragma unroll
    for (int off = 16; off > 0; off >>= 1) ss += __shfl_xor_sync(0xffffffffu, ss, off);
    float inv = 1.f / fmaxf(sqrtf(ss), 1e-12f);
    float a0v = g_a[base + lane], a1v = g_a[base + lane + 32];
    g_nkk[base + lane]      = -kk0 * inv;
    g_nkk[base + lane + 32] = -kk1 * inv;
    g_ab[base + lane]       = kk0 * inv * a0v;
    g_ab[base + lane + 32]  = kk1 * inv * a1v;
    g_knew[base + lane]      = k0v * (1.f + (a0v - 1.f) * kaw[c0]);
    g_knew[base + lane + 32] = k1v * (1.f + (a1v - 1.f) * kaw[c1]);
}

// ---------------- RWKV-7 scan: 128 threads, 2 per state row, packed f32x2 ----------------
__global__ __launch_bounds__(128)
void scan_kernel()
{
    const int bh = blockIdx.x;
    const int b = bh >> 5, h = bh & 31;
    const int tid = threadIdx.x;
    const int j = tid >> 1, half = tid & 1;
    size_t base = (size_t)b * Tn * Cn + h * 64;

    uint64_t S2[16];
    const uint64_t zero2 = pkf2(0.f, 0.f);
#pragma unroll
    for (int i = 0; i < 16; i++) S2[i] = zero2;

    __shared__ float sm[2][384];

    const float* gsrc0;
    const float* gsrc1;
    const float* gsrc2;
    {
        const float* tbl[6] = {g_r, g_wdec, g_knew, g_v, g_nkk, g_ab};
        int l0 = tid, l1 = tid + 128, l2 = tid + 256;
        gsrc0 = tbl[l0 >> 6] + base + (l0 & 63);
        gsrc1 = tbl[l1 >> 6] + base + (l1 & 63);
        gsrc2 = tbl[l2 >> 6] + base + (l2 & 63);
    }
    float f0 = *gsrc0, f1 = *gsrc1, f2 = *gsrc2;

    for (int t = 0; t < Tn; t++) {
        float* sb = sm[t & 1];
        sb[tid] = f0; sb[tid + 128] = f1; sb[tid + 256] = f2;
        __syncthreads();

        if (t + 1 < Tn) {
            gsrc0 += Cn; gsrc1 += Cn; gsrc2 += Cn;
            f0 = *gsrc0; f1 = *gsrc1; f2 = *gsrc2;
        }

        const uint64_t* rv2 = (const uint64_t*)(sb + half * 32);
        const uint64_t* wv2 = (const uint64_t*)(sb + 64 + half * 32);
        const uint64_t* kv2 = (const uint64_t*)(sb + 128 + half * 32);
        const uint64_t* av2 = (const uint64_t*)(sb + 256 + half * 32);
        const uint64_t* bv2 = (const uint64_t*)(sb + 320 + half * 32);

        uint64_t saA = zero2, saB = zero2;
#pragma unroll
        for (int ii = 0; ii < 16; ii += 2) {
            FMA2(saA, S2[ii],     av2[ii],     saA);
            FMA2(saB, S2[ii + 1], av2[ii + 1], saB);
        }
        float s0, s1, s2, s3;
        upkf2(saA, s0, s1); upkf2(saB, s2, s3);
        float sa = (s0 + s1) + (s2 + s3);
        sa += __shfl_xor_sync(0xffffffffu, sa, 1);

        float vj = sb[192 + j];
        uint64_t vj2 = pkf2(vj, vj);
        uint64_t sa2 = pkf2(sa, sa);
        uint64_t yA = zero2, yB = zero2;
#pragma unroll
        for (int ii = 0; ii < 16; ii += 2) {
            uint64_t t0, t1;
            MUL2(t0, vj2, kv2[ii]);
            MUL2(t1, vj2, kv2[ii + 1]);
            FMA2(t0, sa2, bv2[ii],     t0);
            FMA2(t1, sa2, bv2[ii + 1], t1);
            FMA2(S2[ii],     S2[ii],     wv2[ii],     t0);
            FMA2(S2[ii + 1], S2[ii + 1], wv2[ii + 1], t1);
            FMA2(yA, S2[ii],     rv2[ii],     yA);
            FMA2(yB, S2[ii + 1], rv2[ii + 1], yB);
        }
        float y0, y1, y2, y3;
        upkf2(yA, y0, y1); upkf2(yB, y2, y3);
        float y = (y0 + y1) + (y2 + y3);
        y += __shfl_xor_sync(0xffffffffu, y, 1);
        if (!half) g_y[base + (size_t)t * Cn + j] = y;
    }
}

// ---------------- groupnorm + rk bonus + gate -> fp16 tiled ----------------
__global__ __launch_bounds__(128)
void postln_kernel(const float* __restrict__ rkw, const float* __restrict__ lnw,
                   const float* __restrict__ lnb)
{
    const int warp = threadIdx.x >> 5, lane = threadIdx.x & 31;
    const int gid = blockIdx.x * 4 + warp;
    const int h = gid & (Hn - 1);
    const int bt = gid >> 5;
    size_t base = (size_t)gid * 64;
    int c0 = h * 64 + lane, c1 = c0 + 32;

    float y0 = g_y[base + lane], y1 = g_y[base + lane + 32];
    float s = y0 + y1;
#pragma unroll
    for (int off = 16; off > 0; off >>= 1) s += __shfl_xor_sync(0xffffffffu, s, off);
    float mu = s * (1.f / 64.f);
    float d0 = y0 - mu, d1 = y1 - mu;
    float vs = d0 * d0 + d1 * d1;
#pragma unroll
    for (int off = 16; off > 0; off >>= 1) vs += __shfl_xor_sync(0xffffffffu, vs, off);
    float inv = rsqrtf(vs * (1.f / 64.f) + LN_EPS);

    float rk = g_r[base + lane] * g_knew[base + lane] * rkw[c0]
             + g_r[base + lane + 32] * g_knew[base + lane + 32] * rkw[c1];
#pragma unroll
    for (int off = 16; off > 0; off >>= 1) rk += __shfl_xor_sync(0xffffffffu, rk, off);

    float yn0 = d0 * inv * lnw[c0] + lnb[c0];
    float yn1 = d1 * inv * lnw[c1] + lnb[c1];
    float o0 = (yn0 + rk * g_v[base + lane])      * g_g[base + lane];
    float o1 = (yn1 + rk * g_v[base + lane + 32]) * g_g[base + lane + 32];

    int mb = bt >> 7, r = bt & 127;
    g_ygt[tile_idx4(mb, c0 >> 5, r, c0 & 31)] = __float2half(o0);
    g_ygt[tile_idx4(mb, c1 >> 5, r, c1 & 31)] = __float2half(o1);
}

// ---------------- host ----------------
template<typename T> static T* sym(const void* s) { void* p = nullptr; cudaGetSymbolAddress(&p, s); return (T*)p; }

extern "C" void kernel_launch(void* const* d_in, const int* in_sizes, int n_in,
                              void* d_out, int out_size)
{
    const float* x    = (const float*)d_in[0];
    const float* mask = (const float*)d_in[1];
    const float* vf   = (const float*)d_in[2];
    const float* x_r  = (const float*)d_in[3];
    const float* x_w  = (const float*)d_in[4];
    const float* x_k  = (const float*)d_in[5];
    const float* x_v  = (const float*)d_in[6];
    const float* x_a  = (const float*)d_in[7];
    const float* x_g  = (const float*)d_in[8];
    const float* w0   = (const float*)d_in[9];
    const float* w1   = (const float*)d_in[10];
    const float* w2   = (const float*)d_in[11];
    const float* a0   = (const float*)d_in[12];
    const float* a1   = (const float*)d_in[13];
    const float* a2   = (const float*)d_in[14];
    const float* v0   = (const float*)d_in[15];
    const float* v1   = (const float*)d_in[16];
    const float* v2   = (const float*)d_in[17];
    const float* g1   = (const float*)d_in[18];
    const float* g2   = (const float*)d_in[19];
    const float* k_k  = (const float*)d_in[20];
    const float* k_a  = (const float*)d_in[21];
    const float* r_k  = (const float*)d_in[22];
    const float* W_r  = (const float*)d_in[23];
    const float* W_k  = (const float*)d_in[24];
    const float* W_v  = (const float*)d_in[25];
    const float* W_o  = (const float*)d_in[26];
    const float* ln_w = (const float*)d_in[27];
    const float* ln_b = (const float*)d_in[28];

    __half* p_Wo16  = sym<__half>(g_Wo16);
    __half* p_ygt   = sym<__half>(g_ygt);

    float* out = (float*)d_out;

    const unsigned EW2 = (unsigned)((BTC / 2 + 255) / 256);
    const unsigned WW2 = (unsigned)(((size_t)Cn * Cn / 2 + 255) / 256);
    const unsigned TW = (unsigned)((KP * Cn + 255) / 256);
    const int SHB = 3 * 128 * 40 * 2 * 2;
    const int BSH3 = 1024 + 3 * 32768;
    const int BSH1 = 1024 + 6 * 16384;

    cudaFuncSetAttribute(hgemm2, cudaFuncAttributeMaxDynamicSharedMemorySize, SHB);
    cudaFuncSetAttribute(bgemm3, cudaFuncAttributeMaxDynamicSharedMemorySize, BSH3);
    cudaFuncSetAttribute(bgemm1, cudaFuncAttributeMaxDynamicSharedMemorySize, BSH1);

    // weight prep
    conv_wt4<<<dim3(WW2, 4), 256>>>(W_r, W_k, W_v, W_o);
    tsplit_all<<<dim3(TW, 8), 256>>>(w1, a1, v1, g1, w2, a2, v2, g2);

    // mixing
    mix_split<<<EW2, 256>>>(x, mask, x_r, x_w, x_k, x_v, x_a, x_g);

    // merged: k/v (z0..1) + mlp1 (z2..5) + r fp16 with full 6-stage pipeline (z6)
    bgemm3<<<dim3(16, 64, 7), 256, BSH3>>>();

    // mlp2 (4 paths)
    hgemm2<<<dim3(16, 64, 4), 256, SHB>>>(w0, a0, v0);

    // fused v-combine + kk
    kkv_fused<<<BT * Hn / 8, 256>>>(vf, mask, k_k, k_a);

    // scan (128 threads, packed f32x2 — round-13 proven version)
    scan_kernel<<<Bn * Hn, 128>>>();

    // post groupnorm -> fp16 tiled
    postln_kernel<<<BT * Hn / 4, 128>>>(r_k, ln_w, ln_b);

    // output projection: single fp16
    bgemm1<<<dim3(16, 64), 256, BSH1>>>(p_ygt, p_Wo16, out);

    if ((size_t)out_size >= 2 * BTC) {
        cudaMemcpyAsync(out + BTC, vf, BTC * sizeof(float), cudaMemcpyDeviceToDevice, 0);
    }
}

// round 16
// speedup vs baseline: 1.2830x; 1.0366x over previous
#include <cuda_runtime.h>
#include <cuda_bf16.h>
#include <cuda_fp16.h>
#include <math.h>
#include <stdint.h>

#define Bn 8
#define Tn 1024
#define Cn 2048
#define Hn 32
#define BT (Bn*Tn)                 // 8192
#define BTC ((size_t)BT*Cn)        // 16777216
#define LN_EPS (1e-5f*64.0f)
#define KP 128

typedef __nv_bfloat16 bf16;

// ---------------- scratch ----------------
__device__ float g_r[BTC], g_k[BTC], g_v[BTC], g_wdec[BTC], g_a[BTC], g_vg[BTC];
__device__ float g_g[BTC], g_nkk[BTC], g_ab[BTC], g_knew[BTC], g_y[BTC];
__device__ __align__(128) bf16 g_xkt[(size_t)BT*4096], g_xvt[(size_t)BT*4096];
__device__ __align__(128) bf16 g_xwt[(size_t)BT*4096], g_xat[(size_t)BT*4096], g_xgt[(size_t)BT*4096];
__device__ __align__(128) __half g_xrt16[(size_t)BT*2048];
__device__ __align__(128) __half g_ygt[(size_t)BT*2048];
__device__ __align__(128) bf16 g_Wt[2][(size_t)Cn*4096];          // Wk, Wv
__device__ __align__(128) __half g_Wr16[(size_t)Cn*2048];
__device__ __align__(128) __half g_Wo16[(size_t)Cn*2048];
__device__ __align__(128) bf16 g_w1bt[4][(size_t)64*8192];
__device__ __align__(128) bf16 g_w2t[4][(size_t)Cn*2*KP];
__device__ __align__(128) bf16 g_hid4[4][(size_t)BT*256];

// ---------------- helpers ----------------
__device__ __forceinline__ void split_store(bf16* dst, size_t hi_idx, size_t lo_off, float v) {
    bf16 hi = __float2bfloat16(v);
    bf16 lo = __float2bfloat16(v - __bfloat162float(hi));
    dst[hi_idx] = hi;
    dst[hi_idx + lo_off] = lo;
}

__device__ __forceinline__ uint32_t pack2(bf16 a, bf16 b) {
    return ((uint32_t)*(uint16_t*)&b << 16) | (uint32_t)*(uint16_t*)&a;
}

__device__ __forceinline__ void split_store2(bf16* dst, size_t hi_idx, size_t lo_off,
                                             float v0, float v1) {
    bf16 h0 = __float2bfloat16(v0), h1 = __float2bfloat16(v1);
    bf16 l0 = __float2bfloat16(v0 - __bfloat162float(h0));
    bf16 l1 = __float2bfloat16(v1 - __bfloat162float(h1));
    *(uint32_t*)&dst[hi_idx] = pack2(h0, h1);
    *(uint32_t*)&dst[hi_idx + lo_off] = pack2(l0, l1);
}

__device__ __forceinline__ size_t tile_idx8(int mb, int kt, int r, int cc) {
    int slot = (cc >> 3) ^ ((r >> 1) & 3);
    return ((size_t)(mb * 64 + kt)) * 8192 + r * 32 + slot * 8 + (cc & 7);
}
__device__ __forceinline__ size_t tile_idx4(int mb, int kt, int r, int cc) {
    int slot = (cc >> 3) ^ ((r >> 1) & 3);
    return ((size_t)(mb * 64 + kt)) * 4096 + r * 32 + slot * 8 + (cc & 7);
}

__device__ __forceinline__ uint32_t smem_u32(const void* p) {
    return (uint32_t)__cvta_generic_to_shared(p);
}

__device__ __forceinline__ uint64_t pkf2(float a, float b) {
    uint64_t r; asm("mov.b64 %0, {%1, %2};" : "=l"(r) : "f"(a), "f"(b)); return r;
}
__device__ __forceinline__ void upkf2(uint64_t v, float& a, float& b) {
    asm("mov.b64 {%0, %1}, %2;" : "=f"(a), "=f"(b) : "l"(v));
}
#define MUL2(d, a, b)    asm("mul.rn.f32x2 %0, %1, %2;" : "=l"(d) : "l"(a), "l"(b))
#define FMA2(d, a, b, c) asm("fma.rn.f32x2 %0, %1, %2, %3;" : "=l"(d) : "l"(a), "l"(b), "l"(c))

#define MBAR_INIT(addr, cnt) \
    asm volatile("mbarrier.init.shared.b64 [%0], %1;" :: "r"(addr), "r"(cnt) : "memory")
#define MBAR_ARRIVE(addr) \
    asm volatile("mbarrier.arrive.shared.b64 _, [%0];" :: "r"(addr) : "memory")
#define MBAR_EXPECT_TX(addr, bytes) \
    asm volatile("mbarrier.arrive.expect_tx.shared.b64 _, [%0], %1;" :: "r"(addr), "r"(bytes) : "memory")
#define MBAR_WAIT(addr, parity) do { \
    uint32_t _m = (addr), _p = (parity), _d; \
    asm volatile("{\n\t.reg .pred p;\n\tmbarrier.try_wait.parity.acquire.cta.shared::cta.b64 p, [%1], %2;\n\tselp.b32 %0, 1, 0, p;\n\t}" \
        : "=r"(_d) : "r"(_m), "r"(_p) : "memory"); \
    if (!_d) { \
        asm volatile("{\n\t.reg .pred P1;\n\tWL_%=:\n\tmbarrier.try_wait.parity.acquire.cta.shared::cta.b64 P1, [%0], %1, 0x989680;\n\t@P1 bra.uni WD_%=;\n\tbra.uni WL_%=;\n\tWD_%=:\n\t}" \
            :: "r"(_m), "r"(_p) : "memory"); \
    } \
} while (0)

__device__ __forceinline__ void tma_bulk(uint32_t dst, const void* src, uint32_t bytes, uint32_t mbar) {
    asm volatile("cp.async.bulk.shared::cluster.global.mbarrier::complete_tx::bytes [%0], [%1], %2, [%3];"
                 :: "r"(dst), "l"(src), "r"(bytes), "r"(mbar) : "memory");
}

#define LDSM4(r0, r1, r2, r3, addr) \
    asm volatile("ldmatrix.sync.aligned.m8n8.x4.shared.b16 {%0,%1,%2,%3}, [%4];" \
                 : "=r"(r0), "=r"(r1), "=r"(r2), "=r"(r3) : "r"(addr))

#define MMA_BF(c, a, b0, b1) \
    asm volatile("mma.sync.aligned.m16n8k16.row.col.f32.bf16.bf16.f32 " \
                 "{%0,%1,%2,%3}, {%4,%5,%6,%7}, {%8,%9}, {%0,%1,%2,%3};\n" \
                 : "+f"((c)[0]), "+f"((c)[1]), "+f"((c)[2]), "+f"((c)[3]) \
                 : "r"((a)[0]), "r"((a)[1]), "r"((a)[2]), "r"((a)[3]), "r"(b0), "r"(b1))

#define MMA_FP(c, a, b0, b1) \
    asm volatile("mma.sync.aligned.m16n8k16.row.col.f32.f16.f16.f32 " \
                 "{%0,%1,%2,%3}, {%4,%5,%6,%7}, {%8,%9}, {%0,%1,%2,%3};\n" \
                 : "+f"((c)[0]), "+f"((c)[1]), "+f"((c)[2]), "+f"((c)[3]) \
                 : "r"((a)[0]), "r"((a)[1]), "r"((a)[2]), "r"((a)[3]), "r"(b0), "r"(b1))

// ---------------- mixing ----------------
__global__ void mix_split(const float* __restrict__ x, const float* __restrict__ mask,
                          const float* __restrict__ mr, const float* __restrict__ mw,
                          const float* __restrict__ mk, const float* __restrict__ mv,
                          const float* __restrict__ ma, const float* __restrict__ mg)
{
    size_t p = (size_t)blockIdx.x * blockDim.x + threadIdx.x;
    if (p >= BTC / 2) return;
    int cp = (int)(p % (Cn / 2));
    int c = cp * 2;
    size_t bt = p / (Cn / 2);
    int t = (int)(bt % Tn);
    float m = mask[bt];
    float2 xc = *(const float2*)&x[bt * Cn + c];
    float x0 = xc.x * m, x1 = xc.y * m;
    float p0 = 0.f, p1 = 0.f;
    if (t > 0) {
        float mp = mask[bt - 1];
        float2 xpv = *(const float2*)&x[(bt - 1) * Cn + c];
        p0 = xpv.x * mp; p1 = xpv.y * mp;
    }
    float d0 = p0 - x0, d1 = p1 - x1;
    float2 cr = *(const float2*)&mr[c], cw = *(const float2*)&mw[c];
    float2 ck = *(const float2*)&mk[c], cv = *(const float2*)&mv[c];
    float2 ca = *(const float2*)&ma[c], cg = *(const float2*)&mg[c];

    int mb = (int)(bt >> 7), r = (int)(bt & 127), kt = c >> 5, cc = c & 31;
    size_t ti = tile_idx8(mb, kt, r, cc);
    split_store2(g_xkt, ti, 4096, x0 + d0 * ck.x, x1 + d1 * ck.y);
    split_store2(g_xvt, ti, 4096, x0 + d0 * cv.x, x1 + d1 * cv.y);
    split_store2(g_xwt, ti, 4096, x0 + d0 * cw.x, x1 + d1 * cw.y);
    split_store2(g_xat, ti, 4096, x0 + d0 * ca.x, x1 + d1 * ca.y);
    split_store2(g_xgt, ti, 4096, x0 + d0 * cg.x, x1 + d1 * cg.y);

    size_t ti4 = tile_idx4(mb, kt, r, cc);
    __half2 hr = __floats2half2_rn(x0 + d0 * cr.x, x1 + d1 * cr.y);
    *(uint32_t*)&g_xrt16[ti4] = *(uint32_t*)&hr;
}

// ---------------- weight conversions ----------------
__global__ void conv_wt4(const float* __restrict__ Wr, const float* __restrict__ Wk,
                         const float* __restrict__ Wv, const float* __restrict__ Wo)
{
    size_t p = (size_t)blockIdx.x * blockDim.x + threadIdx.x;
    if (p >= (size_t)Cn * Cn / 2) return;
    int z = blockIdx.y;
    int n = (int)(p / (Cn / 2)), k = (int)(p % (Cn / 2)) * 2;
    if (z == 1 || z == 2) {
        const float* src = (z == 1) ? Wk : Wv;
        float2 v = *(const float2*)&src[(size_t)n * Cn + k];
        split_store2(g_Wt[z - 1], tile_idx8(n >> 7, k >> 5, n & 127, k & 31), 4096, v.x, v.y);
    } else {
        const float* src = (z == 0) ? Wr : Wo;
        __half* dst = (z == 0) ? g_Wr16 : g_Wo16;
        float2 v = *(const float2*)&src[(size_t)n * Cn + k];
        __half2 h = __floats2half2_rn(v.x, v.y);
        *(uint32_t*)&dst[tile_idx4(n >> 7, k >> 5, n & 127, k & 31)] = *(uint32_t*)&h;
    }
}

__global__ void tsplit_all(const float* __restrict__ w1, const float* __restrict__ a1,
                           const float* __restrict__ v1, const float* __restrict__ g1,
                           const float* __restrict__ w2, const float* __restrict__ a2,
                           const float* __restrict__ v2, const float* __restrict__ g2)
{
    int i = blockIdx.x * blockDim.x + threadIdx.x;
    if (i >= KP * Cn) return;
    int z = blockIdx.y;
    if (z < 4) {
        const float* in = (z == 0) ? w1 : (z == 1) ? a1 : (z == 2) ? v1 : g1;
        int nd = (z == 2) ? 64 : (z == 3) ? 128 : 96;
        int n = i / Cn, k = i % Cn;
        float v = (n < nd) ? in[(size_t)k * nd + n] : 0.f;
        split_store(g_w1bt[z], tile_idx8(0, k >> 5, n, k & 31), 4096, v);
    } else {
        int zz = z - 4;
        const float* in = (zz == 0) ? w2 : (zz == 1) ? a2 : (zz == 2) ? v2 : g2;
        int nd = (zz == 2) ? 64 : (zz == 3) ? 128 : 96;
        int n = i / KP, k = i % KP;
        float v = (k < nd) ? in[(size_t)k * Cn + n] : 0.f;
        split_store(g_w2t[zz], (size_t)n * (2 * KP) + k, KP, v);
    }
}

// ---------------- merged bulk-TMA GEMM ----------------
// z 0..1: k/v (bf16 3-term, 3 stages x 32KB); z 2..5: mlp1 (bn==0, bf16 3-term);
// z 6: r (fp16 single-segment, 6 stages x 16KB)
__global__ __launch_bounds__(256, 2)
void bgemm3()
{
    const int bn = blockIdx.x, bm = blockIdx.y, z = blockIdx.z;
    if (z >= 2 && z < 6 && bn != 0) return;

    extern __shared__ __align__(1024) char smem[];
    const uint32_t sb = smem_u32(smem);
    const int tid = threadIdx.x, w = tid >> 5, lane = tid & 31;
    const int wm = (w & 3) * 32, wn = (w >> 2) * 64;

    const uint32_t FULL = sb;
    const uint32_t EMPTY = sb + 64;
    const uint32_t ST = sb + 1024;

    if (tid == 0) {
#pragma unroll
        for (int s = 0; s < 6; s++) { MBAR_INIT(FULL + 8 * s, 1); MBAR_INIT(EMPTY + 8 * s, 8); }
    }
    __syncthreads();

    float acc[2][8][4];
#pragma unroll
    for (int mi = 0; mi < 2; mi++)
#pragma unroll
        for (int ni = 0; ni < 8; ni++)
#pragma unroll
            for (int q = 0; q < 4; q++) acc[mi][ni][q] = 0.f;

    if (z == 6) {
        const __half* A = g_xrt16;
        const __half* Bw = g_Wr16;
        if (tid == 0) {
#pragma unroll
            for (int t = 0; t < 5; t++) {
                MBAR_EXPECT_TX(FULL + 8 * t, 16384u);
                tma_bulk(ST + t * 16384,        A  + ((size_t)(bm * 64 + t)) * 4096, 8192u, FULL + 8 * t);
                tma_bulk(ST + t * 16384 + 8192, Bw + ((size_t)(bn * 64 + t)) * 4096, 8192u, FULL + 8 * t);
            }
        }
        for (int t = 0; t < 64; t++) {
            int s = t % 6;
            if (tid == 0 && t + 5 < 64) {
                int tp = t + 5, sp = tp % 6, up = tp / 6;
                if (up >= 1) MBAR_WAIT(EMPTY + 8 * sp, (up - 1) & 1);
                MBAR_EXPECT_TX(FULL + 8 * sp, 16384u);
                tma_bulk(ST + sp * 16384,        A  + ((size_t)(bm * 64 + tp)) * 4096, 8192u, FULL + 8 * sp);
                tma_bulk(ST + sp * 16384 + 8192, Bw + ((size_t)(bn * 64 + tp)) * 4096, 8192u, FULL + 8 * sp);
            }
            MBAR_WAIT(FULL + 8 * s, (t / 6) & 1);
            const uint32_t st = ST + s * 16384;
#pragma unroll
            for (int kk = 0; kk < 32; kk += 16) {
                uint32_t af[2][4];
#pragma unroll
                for (int mi = 0; mi < 2; mi++) {
                    int rr = wm + mi * 16 + (lane & 15);
                    int c8 = (kk >> 3) + (lane >> 4);
                    int slot = c8 ^ ((rr >> 1) & 3);
                    LDSM4(af[mi][0], af[mi][1], af[mi][2], af[mi][3],
                          st + (uint32_t)(rr * 64 + slot * 16));
                }
#pragma unroll
                for (int n2 = 0; n2 < 4; n2++) {
                    int rb = wn + n2 * 16 + (lane & 7) + ((lane & 16) ? 8 : 0);
                    int c8 = (kk >> 3) + ((lane & 8) ? 1 : 0);
                    int slot = c8 ^ ((rb >> 1) & 3);
                    uint32_t bq[4];
                    LDSM4(bq[0], bq[1], bq[2], bq[3],
                          st + 8192 + (uint32_t)(rb * 64 + slot * 16));
#pragma unroll
                    for (int mi = 0; mi < 2; mi++) {
                        MMA_FP(acc[mi][2 * n2],     af[mi], bq[0], bq[1]);
                        MMA_FP(acc[mi][2 * n2 + 1], af[mi], bq[2], bq[3]);
                    }
                }
            }
            if (lane == 0) MBAR_ARRIVE(EMPTY + 8 * s);
        }
#pragma unroll
        for (int mi = 0; mi < 2; mi++)
#pragma unroll
            for (int ni = 0; ni < 8; ni++) {
                int row = bm * 128 + wm + mi * 16 + (lane >> 2);
                int col = bn * 128 + wn + ni * 8 + (lane & 3) * 2;
                float* c = acc[mi][ni];
                g_r[(size_t)row * Cn + col]           = c[0];
                g_r[(size_t)row * Cn + col + 1]       = c[1];
                g_r[(size_t)(row + 8) * Cn + col]     = c[2];
                g_r[(size_t)(row + 8) * Cn + col + 1] = c[3];
            }
        return;
    }

    const bf16* A;
    const bf16* Bw;
    if (z < 2) {
        A = (z == 0) ? g_xkt : g_xvt;
        Bw = g_Wt[z];
    } else {
        A = (z == 2) ? g_xwt : (z == 3) ? g_xat : (z == 4) ? g_xvt : g_xgt;
        Bw = g_w1bt[z - 2];
    }

    if (tid == 0) {
#pragma unroll
        for (int t = 0; t < 2; t++) {
            MBAR_EXPECT_TX(FULL + 8 * t, 32768u);
            tma_bulk(ST + t * 32768,         A  + ((size_t)(bm * 64 + t)) * 8192, 16384u, FULL + 8 * t);
            tma_bulk(ST + t * 32768 + 16384, Bw + ((size_t)(bn * 64 + t)) * 8192, 16384u, FULL + 8 * t);
        }
    }

    for (int t = 0; t < 64; t++) {
        int s = t % 3;
        if (tid == 0 && t + 2 < 64) {
            int tp = t + 2, sp = tp % 3, up = tp / 3;
            if (up >= 1) MBAR_WAIT(EMPTY + 8 * sp, (up - 1) & 1);
            MBAR_EXPECT_TX(FULL + 8 * sp, 32768u);
            tma_bulk(ST + sp * 32768,         A  + ((size_t)(bm * 64 + tp)) * 8192, 16384u, FULL + 8 * sp);
            tma_bulk(ST + sp * 32768 + 16384, Bw + ((size_t)(bn * 64 + tp)) * 8192, 16384u, FULL + 8 * sp);
        }
        MBAR_WAIT(FULL + 8 * s, (t / 3) & 1);
        const uint32_t st = ST + s * 32768;

#pragma unroll
        for (int kk = 0; kk < 32; kk += 16) {
            uint32_t ah[2][4], al[2][4];
#pragma unroll
            for (int mi = 0; mi < 2; mi++) {
                int rr = wm + mi * 16 + (lane & 15);
                int c8 = (kk >> 3) + (lane >> 4);
                int slot = c8 ^ ((rr >> 1) & 3);
                uint32_t ad = st + (uint32_t)(rr * 64 + slot * 16);
                LDSM4(ah[mi][0], ah[mi][1], ah[mi][2], ah[mi][3], ad);
                LDSM4(al[mi][0], al[mi][1], al[mi][2], al[mi][3], ad + 8192);
            }
#pragma unroll
            for (int n2 = 0; n2 < 4; n2++) {
                int rb = wn + n2 * 16 + (lane & 7) + ((lane & 16) ? 8 : 0);
                int c8 = (kk >> 3) + ((lane & 8) ? 1 : 0);
                int slot = c8 ^ ((rb >> 1) & 3);
                uint32_t bd = st + 16384 + (uint32_t)(rb * 64 + slot * 16);
                uint32_t bh[4], bl[4];
                LDSM4(bh[0], bh[1], bh[2], bh[3], bd);
                LDSM4(bl[0], bl[1], bl[2], bl[3], bd + 8192);
#pragma unroll
                for (int mi = 0; mi < 2; mi++) {
                    MMA_BF(acc[mi][2 * n2],     ah[mi], bh[0], bh[1]);
                    MMA_BF(acc[mi][2 * n2 + 1], ah[mi], bh[2], bh[3]);
                    MMA_BF(acc[mi][2 * n2],     al[mi], bh[0], bh[1]);
                    MMA_BF(acc[mi][2 * n2 + 1], al[mi], bh[2], bh[3]);
                    MMA_BF(acc[mi][2 * n2],     ah[mi], bl[0], bl[1]);
                    MMA_BF(acc[mi][2 * n2 + 1], ah[mi], bl[2], bl[3]);
                }
            }
        }
        if (lane == 0) MBAR_ARRIVE(EMPTY + 8 * s);
    }

#pragma unroll
    for (int mi = 0; mi < 2; mi++)
#pragma unroll
        for (int ni = 0; ni < 8; ni++) {
            int row = bm * 128 + wm + mi * 16 + (lane >> 2);
            int col = bn * 128 + wn + ni * 8 + (lane & 3) * 2;
            float* c = acc[mi][ni];
            if (z < 2) {
                float* C = (z == 0) ? g_k : g_v;
                C[(size_t)row * Cn + col]           = c[0];
                C[(size_t)row * Cn + col + 1]       = c[1];
                C[(size_t)(row + 8) * Cn + col]     = c[2];
                C[(size_t)(row + 8) * Cn + col + 1] = c[3];
            } else {
                bf16* hid = g_hid4[z - 2];
                auto act = [&](float v) -> float {
                    if (z == 2) return tanhf(v);
                    if (z == 5) return 1.f / (1.f + expf(-v));
                    return v;
                };
                split_store(hid, (size_t)row * 256 + col,           KP, act(c[0]));
                split_store(hid, (size_t)row * 256 + col + 1,       KP, act(c[1]));
                split_store(hid, (size_t)(row + 8) * 256 + col,     KP, act(c[2]));
                split_store(hid, (size_t)(row + 8) * 256 + col + 1, KP, act(c[3]));
            }
        }
}

// ---------------- bulk-TMA fp16 single GEMM (out-proj) ----------------
__global__ __launch_bounds__(256, 2)
void bgemm1(const __half* __restrict__ A, const __half* __restrict__ Bw,
            float* __restrict__ C)
{
    extern __shared__ __align__(1024) char smem[];
    const uint32_t sb = smem_u32(smem);
    const int tid = threadIdx.x, w = tid >> 5, lane = tid & 31;
    const int bn = blockIdx.x, bm = blockIdx.y;
    const int wm = (w & 3) * 32, wn = (w >> 2) * 64;

    const uint32_t FULL = sb;
    const uint32_t EMPTY = sb + 64;
    const uint32_t ST = sb + 1024;

    if (tid == 0) {
#pragma unroll
        for (int s = 0; s < 6; s++) { MBAR_INIT(FULL + 8 * s, 1); MBAR_INIT(EMPTY + 8 * s, 8); }
    }
    __syncthreads();

    if (tid == 0) {
#pragma unroll
        for (int t = 0; t < 5; t++) {
            MBAR_EXPECT_TX(FULL + 8 * t, 16384u);
            tma_bulk(ST + t * 16384,        A  + ((size_t)(bm * 64 + t)) * 4096, 8192u, FULL + 8 * t);
            tma_bulk(ST + t * 16384 + 8192, Bw + ((size_t)(bn * 64 + t)) * 4096, 8192u, FULL + 8 * t);
        }
    }

    float acc[2][8][4];
#pragma unroll
    for (int mi = 0; mi < 2; mi++)
#pragma unroll
        for (int ni = 0; ni < 8; ni++)
#pragma unroll
            for (int q = 0; q < 4; q++) acc[mi][ni][q] = 0.f;

    for (int t = 0; t < 64; t++) {
        int s = t % 6;
        if (tid == 0 && t + 5 < 64) {
            int tp = t + 5, sp = tp % 6, up = tp / 6;
            if (up >= 1) MBAR_WAIT(EMPTY + 8 * sp, (up - 1) & 1);
            MBAR_EXPECT_TX(FULL + 8 * sp, 16384u);
            tma_bulk(ST + sp * 16384,        A  + ((size_t)(bm * 64 + tp)) * 4096, 8192u, FULL + 8 * sp);
            tma_bulk(ST + sp * 16384 + 8192, Bw + ((size_t)(bn * 64 + tp)) * 4096, 8192u, FULL + 8 * sp);
        }
        MBAR_WAIT(FULL + 8 * s, (t / 6) & 1);
        const uint32_t st = ST + s * 16384;

#pragma unroll
        for (int kk = 0; kk < 32; kk += 16) {
            uint32_t af[2][4];
#pragma unroll
            for (int mi = 0; mi < 2; mi++) {
                int rr = wm + mi * 16 + (lane & 15);
                int c8 = (kk >> 3) + (lane >> 4);
                int slot = c8 ^ ((rr >> 1) & 3);
                LDSM4(af[mi][0], af[mi][1], af[mi][2], af[mi][3],
                      st + (uint32_t)(rr * 64 + slot * 16));
            }
#pragma unroll
            for (int n2 = 0; n2 < 4; n2++) {
                int rb = wn + n2 * 16 + (lane & 7) + ((lane & 16) ? 8 : 0);
                int c8 = (kk >> 3) + ((lane & 8) ? 1 : 0);
                int slot = c8 ^ ((rb >> 1) & 3);
                uint32_t bq[4];
                LDSM4(bq[0], bq[1], bq[2], bq[3],
                      st + 8192 + (uint32_t)(rb * 64 + slot * 16));
#pragma unroll
                for (int mi = 0; mi < 2; mi++) {
                    MMA_FP(acc[mi][2 * n2],     af[mi], bq[0], bq[1]);
                    MMA_FP(acc[mi][2 * n2 + 1], af[mi], bq[2], bq[3]);
                }
            }
        }
        if (lane == 0) MBAR_ARRIVE(EMPTY + 8 * s);
    }

#pragma unroll
    for (int mi = 0; mi < 2; mi++)
#pragma unroll
        for (int ni = 0; ni < 8; ni++) {
            int row = bm * 128 + wm + mi * 16 + (lane >> 2);
            int col = bn * 128 + wn + ni * 8 + (lane & 3) * 2;
            float* c = acc[mi][ni];
            C[(size_t)row * Cn + col]           = c[0];
            C[(size_t)row * Cn + col + 1]       = c[1];
            C[(size_t)(row + 8) * Cn + col]     = c[2];
            C[(size_t)(row + 8) * Cn + col + 1] = c[3];
        }
}

// ---------------- mma.sync split-bf16 GEMM for MLP2 ----------------
__global__ __launch_bounds__(256, 2)
void hgemm2(const float* __restrict__ b0, const float* __restrict__ b1,
            const float* __restrict__ b2)
{
    constexpr int TPS = 4;
    constexpr int KT  = 12;
    constexpr int SSZ = 128 * 40;
    extern __shared__ bf16 sh[];
    bf16* As = sh;
    bf16* Bs = sh + 3 * SSZ;

    const int tid = threadIdx.x;
    const int z = blockIdx.z;
    const int bm = blockIdx.y * 128, bn = blockIdx.x * 128;
    const int w = tid >> 5, lane = tid & 31;
    const int wm = (w & 3) * 32, wn = (w >> 2) * 64;

    const bf16* A = g_hid4[z];
    const bf16* Bw = g_w2t[z];

    float acc[2][8][4];
#pragma unroll
    for (int mi = 0; mi < 2; mi++)
#pragma unroll
        for (int ni = 0; ni < 8; ni++)
#pragma unroll
            for (int q = 0; q < 4; q++) acc[mi][ni][q] = 0.f;

    auto loadtile = [&](int stage, int t) {
        int seg = t / TPS, kk = (t % TPS) * 32;
        int aoff = (seg == 1 ? 128 : 0) + kk;
        int boff = (seg == 2 ? 128 : 0) + kk;
        bf16* as = As + stage * SSZ;
        bf16* bs = Bs + stage * SSZ;
#pragma unroll
        for (int c = 0; c < 2; c++) {
            int ch = tid + c * 256;
            int row = ch >> 2, col = ch & 3;
            unsigned sa = (unsigned)__cvta_generic_to_shared(&as[row * 40 + col * 8]);
            const void* ga = &A[(size_t)(bm + row) * 256 + aoff + col * 8];
            asm volatile("cp.async.cg.shared.global [%0], [%1], 16;\n" :: "r"(sa), "l"(ga));
            unsigned sb2 = (unsigned)__cvta_generic_to_shared(&bs[row * 40 + col * 8]);
            const void* gb = &Bw[(size_t)(bn + row) * 256 + boff + col * 8];
            asm volatile("cp.async.cg.shared.global [%0], [%1], 16;\n" :: "r"(sb2), "l"(gb));
        }
        asm volatile("cp.async.commit_group;\n" ::: "memory");
    };

    loadtile(0, 0);
    loadtile(1, 1);

    const int arow = wm + (lane & 15);
    const int acolo = (lane >> 4) << 3;
    const int brow = (lane & 7) + ((lane & 16) ? 8 : 0);
    const int bcolo = (lane & 8) ? 8 : 0;

    for (int t = 0; t < KT; t++) {
        if (t + 1 < KT) {
            asm volatile("cp.async.wait_group 1;\n" ::: "memory");
        } else {
            asm volatile("cp.async.wait_group 0;\n" ::: "memory");
        }
        __syncthreads();
        if (t + 2 < KT) loadtile((t + 2) % 3, t + 2);

        const bf16* as = As + (t % 3) * SSZ;
        const bf16* bs = Bs + (t % 3) * SSZ;
        unsigned abase = (unsigned)__cvta_generic_to_shared(as);
        unsigned bbase = (unsigned)__cvta_generic_to_shared(bs);

#pragma unroll
        for (int kk = 0; kk < 32; kk += 16) {
            uint32_t af[2][4];
#pragma unroll
            for (int mi = 0; mi < 2; mi++) {
                unsigned aaddr = abase + (unsigned)(((arow + mi * 16) * 40 + kk + acolo) * 2);
                LDSM4(af[mi][0], af[mi][1], af[mi][2], af[mi][3], aaddr);
            }
            uint32_t bq[4][4];
#pragma unroll
            for (int n2 = 0; n2 < 4; n2++) {
                unsigned baddr = bbase + (unsigned)(((wn + n2 * 16 + brow) * 40 + kk + bcolo) * 2);
                LDSM4(bq[n2][0], bq[n2][1], bq[n2][2], bq[n2][3], baddr);
            }
#pragma unroll
            for (int n2 = 0; n2 < 4; n2++) {
#pragma unroll
                for (int mi = 0; mi < 2; mi++) {
                    MMA_BF(acc[mi][2 * n2],     af[mi], bq[n2][0], bq[n2][1]);
                    MMA_BF(acc[mi][2 * n2 + 1], af[mi], bq[n2][2], bq[n2][3]);
                }
            }
        }
        __syncthreads();
    }

#pragma unroll
    for (int mi = 0; mi < 2; mi++)
#pragma unroll
        for (int ni = 0; ni < 8; ni++) {
            int row = bm + wm + mi * 16 + (lane >> 2);
            int col = bn + wn + ni * 8 + (lane & 3) * 2;
            float* c = acc[mi][ni];
            float* dst = (z == 0) ? g_wdec : (z == 1) ? g_a : (z == 2) ? g_vg : g_g;
            auto epi = [&](float v, int n) -> float {
                if (z == 0) return expf(-0.60653066f / (1.f + expf(-(b0[n] + v))));
                if (z == 1) return 1.f / (1.f + expf(-(b1[n] + v)));
                if (z == 2) return 1.f / (1.f + expf(-(b2[n] + v)));
                return v;
            };
            dst[(size_t)row * Cn + col]           = epi(c[0], col);
            dst[(size_t)row * Cn + col + 1]       = epi(c[1], col + 1);
            dst[(size_t)(row + 8) * Cn + col]     = epi(c[2], col);
            dst[(size_t)(row + 8) * Cn + col + 1] = epi(c[3], col + 1);
        }
}

// ---------------- fused: v-combine + kk-normalize + k-update ----------------
__global__ __launch_bounds__(256)
void kkv_fused(const float* __restrict__ vf, const float* __restrict__ mask,
               const float* __restrict__ kkw, const float* __restrict__ kaw)
{
    const int warp = threadIdx.x >> 5, lane = threadIdx.x & 31;
    const int gid = blockIdx.x * 8 + warp;
    const int h = gid & (Hn - 1);
    const int bt = gid >> 5;
    size_t base = (size_t)gid * 64;
    int c0 = h * 64 + lane, c1 = c0 + 32;
    float m = mask[bt];

    float v0v = g_v[base + lane], v1v = g_v[base + lane + 32];
    float gt0 = g_vg[base + lane], gt1 = g_vg[base + lane + 32];
    v0v = (v0v + (vf[base + lane] - v0v) * gt0) * m;
    v1v = (v1v + (vf[base + lane + 32] - v1v) * gt1) * m;
    g_v[base + lane] = v0v;
    g_v[base + lane + 32] = v1v;

    float k0v = g_k[base + lane], k1v = g_k[base + lane + 32];
    float kk0 = k0v * kkw[c0], kk1 = k1v * kkw[c1];
    float ss = kk0 * kk0 + kk1 * kk1;
#pragma unroll
    for (int off = 16; off > 0; off >>= 1) ss += __shfl_xor_sync(0xffffffffu, ss, off);
    float inv = 1.f / fmaxf(sqrtf(ss), 1e-12f);
    float a0v = g_a[base + lane], a1v = g_a[base + lane + 32];
    g_nkk[base + lane]      = -kk0 * inv;
    g_nkk[base + lane + 32] = -kk1 * inv;
    g_ab[base + lane]       = kk0 * inv * a0v;
    g_ab[base + lane + 32]  = kk1 * inv * a1v;
    g_knew[base + lane]      = k0v * (1.f + (a0v - 1.f) * kaw[c0]);
    g_knew[base + lane + 32] = k1v * (1.f + (a1v - 1.f) * kaw[c1]);
}

// ---------------- RWKV-7 scan: 128 threads, packed f32x2, prefetch depth 2 ----------------
__device__ __forceinline__ void scan_step(float* sb, uint64_t* S2, int tid, int j, int half,
                                          size_t ybase)
{
    const uint64_t zero2 = pkf2(0.f, 0.f);
    const uint64_t* rv2 = (const uint64_t*)(sb + half * 32);
    const uint64_t* wv2 = (const uint64_t*)(sb + 64 + half * 32);
    const uint64_t* kv2 = (const uint64_t*)(sb + 128 + half * 32);
    const uint64_t* av2 = (const uint64_t*)(sb + 256 + half * 32);
    const uint64_t* bv2 = (const uint64_t*)(sb + 320 + half * 32);

    uint64_t saA = zero2, saB = zero2;
#pragma unroll
    for (int ii = 0; ii < 16; ii += 2) {
        FMA2(saA, S2[ii],     av2[ii],     saA);
        FMA2(saB, S2[ii + 1], av2[ii + 1], saB);
    }
    float s0, s1, s2, s3;
    upkf2(saA, s0, s1); upkf2(saB, s2, s3);
    float sa = (s0 + s1) + (s2 + s3);
    sa += __shfl_xor_sync(0xffffffffu, sa, 1);

    float vj = sb[192 + j];
    uint64_t vj2 = pkf2(vj, vj);
    uint64_t sa2 = pkf2(sa, sa);
    uint64_t yA = zero2, yB = zero2;
#pragma unroll
    for (int ii = 0; ii < 16; ii += 2) {
        uint64_t t0, t1;
        MUL2(t0, vj2, kv2[ii]);
        MUL2(t1, vj2, kv2[ii + 1]);
        FMA2(t0, sa2, bv2[ii],     t0);
        FMA2(t1, sa2, bv2[ii + 1], t1);
        FMA2(S2[ii],     S2[ii],     wv2[ii],     t0);
        FMA2(S2[ii + 1], S2[ii + 1], wv2[ii + 1], t1);
        FMA2(yA, S2[ii],     rv2[ii],     yA);
        FMA2(yB, S2[ii + 1], rv2[ii + 1], yB);
    }
    float y0, y1, y2, y3;
    upkf2(yA, y0, y1); upkf2(yB, y2, y3);
    float y = (y0 + y1) + (y2 + y3);
    y += __shfl_xor_sync(0xffffffffu, y, 1);
    if (!half) g_y[ybase + j] = y;
}

__global__ __launch_bounds__(128)
void scan_kernel()
{
    const int bh = blockIdx.x;
    const int b = bh >> 5, h = bh & 31;
    const int tid = threadIdx.x;
    const int j = tid >> 1, half = tid & 1;
    size_t base = (size_t)b * Tn * Cn + h * 64;

    uint64_t S2[16];
    const uint64_t zero2 = pkf2(0.f, 0.f);
#pragma unroll
    for (int i = 0; i < 16; i++) S2[i] = zero2;

    __shared__ float sm[2][384];

    const float* gsrc0;
    const float* gsrc1;
    const float* gsrc2;
    {
        const float* tbl[6] = {g_r, g_wdec, g_knew, g_v, g_nkk, g_ab};
        int l0 = tid, l1 = tid + 128, l2 = tid + 256;
        gsrc0 = tbl[l0 >> 6] + base + (l0 & 63);
        gsrc1 = tbl[l1 >> 6] + base + (l1 & 63);
        gsrc2 = tbl[l2 >> 6] + base + (l2 & 63);
    }
    // prefetch t=0 into set A and t=1 into set B
    float fa0 = gsrc0[0],  fa1 = gsrc1[0],  fa2 = gsrc2[0];
    float fb0 = gsrc0[Cn], fb1 = gsrc1[Cn], fb2 = gsrc2[Cn];
    gsrc0 += 2 * Cn; gsrc1 += 2 * Cn; gsrc2 += 2 * Cn;

    for (int t = 0; t < Tn; t += 2) {
        // even step: consume set A, prefetch t+2 into A
        {
            float* sb = sm[0];
            sb[tid] = fa0; sb[tid + 128] = fa1; sb[tid + 256] = fa2;
            __syncthreads();
            if (t + 2 < Tn) {
                fa0 = gsrc0[0]; fa1 = gsrc1[0]; fa2 = gsrc2[0];
                gsrc0 += Cn; gsrc1 += Cn; gsrc2 += Cn;
            }
            scan_step(sb, S2, tid, j, half, base + (size_t)t * Cn);
        }
        // odd step: consume set B, prefetch t+3 into B
        {
            float* sb = sm[1];
            sb[tid] = fb0; sb[tid + 128] = fb1; sb[tid + 256] = fb2;
            __syncthreads();
            if (t + 3 < Tn) {
                fb0 = gsrc0[0]; fb1 = gsrc1[0]; fb2 = gsrc2[0];
                gsrc0 += Cn; gsrc1 += Cn; gsrc2 += Cn;
            }
            scan_step(sb, S2, tid, j, half, base + (size_t)(t + 1) * Cn);
        }
    }
}

// ---------------- groupnorm + rk bonus + gate -> fp16 tiled ----------------
__global__ __launch_bounds__(128)
void postln_kernel(const float* __restrict__ rkw, const float* __restrict__ lnw,
                   const float* __restrict__ lnb)
{
    const int warp = threadIdx.x >> 5, lane = threadIdx.x & 31;
    const int gid = blockIdx.x * 4 + warp;
    const int h = gid & (Hn - 1);
    const int bt = gid >> 5;
    size_t base = (size_t)gid * 64;
    int c0 = h * 64 + lane, c1 = c0 + 32;

    float y0 = g_y[base + lane], y1 = g_y[base + lane + 32];
    float s = y0 + y1;
#pragma unroll
    for (int off = 16; off > 0; off >>= 1) s += __shfl_xor_sync(0xffffffffu, s, off);
    float mu = s * (1.f / 64.f);
    float d0 = y0 - mu, d1 = y1 - mu;
    float vs = d0 * d0 + d1 * d1;
#pragma unroll
    for (int off = 16; off > 0; off >>= 1) vs += __shfl_xor_sync(0xffffffffu, vs, off);
    float inv = rsqrtf(vs * (1.f / 64.f) + LN_EPS);

    float rk = g_r[base + lane] * g_knew[base + lane] * rkw[c0]
             + g_r[base + lane + 32] * g_knew[base + lane + 32] * rkw[c1];
#pragma unroll
    for (int off = 16; off > 0; off >>= 1) rk += __shfl_xor_sync(0xffffffffu, rk, off);

    float yn0 = d0 * inv * lnw[c0] + lnb[c0];
    float yn1 = d1 * inv * lnw[c1] + lnb[c1];
    float o0 = (yn0 + rk * g_v[base + lane])      * g_g[base + lane];
    float o1 = (yn1 + rk * g_v[base + lane + 32]) * g_g[base + lane + 32];

    int mb = bt >> 7, r = bt & 127;
    g_ygt[tile_idx4(mb, c0 >> 5, r, c0 & 31)] = __float2half(o0);
    g_ygt[tile_idx4(mb, c1 >> 5, r, c1 & 31)] = __float2half(o1);
}

// ---------------- host ----------------
template<typename T> static T* sym(const void* s) { void* p = nullptr; cudaGetSymbolAddress(&p, s); return (T*)p; }

extern "C" void kernel_launch(void* const* d_in, const int* in_sizes, int n_in,
                              void* d_out, int out_size)
{
    const float* x    = (const float*)d_in[0];
    const float* mask = (const float*)d_in[1];
    const float* vf   = (const float*)d_in[2];
    const float* x_r  = (const float*)d_in[3];
    const float* x_w  = (const float*)d_in[4];
    const float* x_k  = (const float*)d_in[5];
    const float* x_v  = (const float*)d_in[6];
    const float* x_a  = (const float*)d_in[7];
    const float* x_g  = (const float*)d_in[8];
    const float* w0   = (const float*)d_in[9];
    const float* w1   = (const float*)d_in[10];
    const float* w2   = (const float*)d_in[11];
    const float* a0   = (const float*)d_in[12];
    const float* a1   = (const float*)d_in[13];
    const float* a2   = (const float*)d_in[14];
    const float* v0   = (const float*)d_in[15];
    const float* v1   = (const float*)d_in[16];
    const float* v2   = (const float*)d_in[17];
    const float* g1   = (const float*)d_in[18];
    const float* g2   = (const float*)d_in[19];
    const float* k_k  = (const float*)d_in[20];
    const float* k_a  = (const float*)d_in[21];
    const float* r_k  = (const float*)d_in[22];
    const float* W_r  = (const float*)d_in[23];
    const float* W_k  = (const float*)d_in[24];
    const float* W_v  = (const float*)d_in[25];
    const float* W_o  = (const float*)d_in[26];
    const float* ln_w = (const float*)d_in[27];
    const float* ln_b = (const float*)d_in[28];

    __half* p_Wo16  = sym<__half>(g_Wo16);
    __half* p_ygt   = sym<__half>(g_ygt);

    float* out = (float*)d_out;

    const unsigned EW2 = (unsigned)((BTC / 2 + 255) / 256);
    const unsigned WW2 = (unsigned)(((size_t)Cn * Cn / 2 + 255) / 256);
    const unsigned TW = (unsigned)((KP * Cn + 255) / 256);
    const int SHB = 3 * 128 * 40 * 2 * 2;
    const int BSH3 = 1024 + 3 * 32768;
    const int BSH1 = 1024 + 6 * 16384;

    cudaFuncSetAttribute(hgemm2, cudaFuncAttributeMaxDynamicSharedMemorySize, SHB);
    cudaFuncSetAttribute(bgemm3, cudaFuncAttributeMaxDynamicSharedMemorySize, BSH3);
    cudaFuncSetAttribute(bgemm1, cudaFuncAttributeMaxDynamicSharedMemorySize, BSH1);

    // weight prep
    conv_wt4<<<dim3(WW2, 4), 256>>>(W_r, W_k, W_v, W_o);
    tsplit_all<<<dim3(TW, 8), 256>>>(w1, a1, v1, g1, w2, a2, v2, g2);

    // mixing
    mix_split<<<EW2, 256>>>(x, mask, x_r, x_w, x_k, x_v, x_a, x_g);

    // merged: k/v (z0..1) + mlp1 (z2..5) + r fp16 6-stage (z6)
    bgemm3<<<dim3(16, 64, 7), 256, BSH3>>>();

    // mlp2 (4 paths)
    hgemm2<<<dim3(16, 64, 4), 256, SHB>>>(w0, a0, v0);

    // fused v-combine + kk
    kkv_fused<<<BT * Hn / 8, 256>>>(vf, mask, k_k, k_a);

    // scan (prefetch depth 2)
    scan_kernel<<<Bn * Hn, 128>>>();

    // post groupnorm -> fp16 tiled
    postln_kernel<<<BT * Hn / 4, 128>>>(r_k, ln_w, ln_b);

    // output projection: single fp16
    bgemm1<<<dim3(16, 64), 256, BSH1>>>(p_ygt, p_Wo16, out);

    if ((size_t)out_size >= 2 * BTC) {
        cudaMemcpyAsync(out + BTC, vf, BTC * sizeof(float), cudaMemcpyDeviceToDevice, 0);
    }
}

// round 17
// speedup vs baseline: 1.2995x; 1.0128x over previous
#include <cuda_runtime.h>
#include <cuda_bf16.h>
#include <cuda_fp16.h>
#include <math.h>
#include <stdint.h>

#define Bn 8
#define Tn 1024
#define Cn 2048
#define Hn 32
#define BT (Bn*Tn)                 // 8192
#define BTC ((size_t)BT*Cn)        // 16777216
#define LN_EPS (1e-5f*64.0f)
#define KP 128

typedef __nv_bfloat16 bf16;

// ---------------- scratch ----------------
__device__ float g_r[BTC], g_k[BTC], g_v[BTC], g_wdec[BTC], g_a[BTC], g_vg[BTC];
__device__ float g_g[BTC], g_nkk[BTC], g_ab[BTC], g_knew[BTC], g_y[BTC];
__device__ __align__(128) bf16 g_xkt[(size_t)BT*4096], g_xvt[(size_t)BT*4096];
__device__ __align__(128) bf16 g_xwt[(size_t)BT*4096], g_xat[(size_t)BT*4096], g_xgt[(size_t)BT*4096];
__device__ __align__(128) __half g_xrt16[(size_t)BT*2048];
__device__ __align__(128) __half g_ygt[(size_t)BT*2048];
__device__ __align__(128) bf16 g_Wt[2][(size_t)Cn*4096];          // Wk, Wv
__device__ __align__(128) __half g_Wr16[(size_t)Cn*2048];
__device__ __align__(128) __half g_Wo16[(size_t)Cn*2048];
__device__ __align__(128) bf16 g_w1bt[4][(size_t)64*8192];
__device__ __align__(128) bf16 g_w2t[4][(size_t)Cn*2*KP];
__device__ __align__(128) bf16 g_hid4[4][(size_t)BT*256];

// ---------------- helpers ----------------
__device__ __forceinline__ void split_store(bf16* dst, size_t hi_idx, size_t lo_off, float v) {
    bf16 hi = __float2bfloat16(v);
    bf16 lo = __float2bfloat16(v - __bfloat162float(hi));
    dst[hi_idx] = hi;
    dst[hi_idx + lo_off] = lo;
}

__device__ __forceinline__ uint32_t pack2(bf16 a, bf16 b) {
    return ((uint32_t)*(uint16_t*)&b << 16) | (uint32_t)*(uint16_t*)&a;
}

// 4-wide split store: indices hi_idx..hi_idx+3 contiguous, 8B-aligned
__device__ __forceinline__ void split_store4(bf16* dst, size_t hi_idx, size_t lo_off,
                                             float v0, float v1, float v2, float v3) {
    bf16 h0 = __float2bfloat16(v0), h1 = __float2bfloat16(v1);
    bf16 h2 = __float2bfloat16(v2), h3 = __float2bfloat16(v3);
    bf16 l0 = __float2bfloat16(v0 - __bfloat162float(h0));
    bf16 l1 = __float2bfloat16(v1 - __bfloat162float(h1));
    bf16 l2 = __float2bfloat16(v2 - __bfloat162float(h2));
    bf16 l3 = __float2bfloat16(v3 - __bfloat162float(h3));
    uint2 hv = make_uint2(pack2(h0, h1), pack2(h2, h3));
    uint2 lv = make_uint2(pack2(l0, l1), pack2(l2, l3));
    *(uint2*)&dst[hi_idx] = hv;
    *(uint2*)&dst[hi_idx + lo_off] = lv;
}

__device__ __forceinline__ size_t tile_idx8(int mb, int kt, int r, int cc) {
    int slot = (cc >> 3) ^ ((r >> 1) & 3);
    return ((size_t)(mb * 64 + kt)) * 8192 + r * 32 + slot * 8 + (cc & 7);
}
__device__ __forceinline__ size_t tile_idx4(int mb, int kt, int r, int cc) {
    int slot = (cc >> 3) ^ ((r >> 1) & 3);
    return ((size_t)(mb * 64 + kt)) * 4096 + r * 32 + slot * 8 + (cc & 7);
}

__device__ __forceinline__ uint32_t smem_u32(const void* p) {
    return (uint32_t)__cvta_generic_to_shared(p);
}

__device__ __forceinline__ uint64_t pkf2(float a, float b) {
    uint64_t r; asm("mov.b64 %0, {%1, %2};" : "=l"(r) : "f"(a), "f"(b)); return r;
}
__device__ __forceinline__ void upkf2(uint64_t v, float& a, float& b) {
    asm("mov.b64 {%0, %1}, %2;" : "=f"(a), "=f"(b) : "l"(v));
}
#define MUL2(d, a, b)    asm("mul.rn.f32x2 %0, %1, %2;" : "=l"(d) : "l"(a), "l"(b))
#define FMA2(d, a, b, c) asm("fma.rn.f32x2 %0, %1, %2, %3;" : "=l"(d) : "l"(a), "l"(b), "l"(c))

#define MBAR_INIT(addr, cnt) \
    asm volatile("mbarrier.init.shared.b64 [%0], %1;" :: "r"(addr), "r"(cnt) : "memory")
#define MBAR_ARRIVE(addr) \
    asm volatile("mbarrier.arrive.shared.b64 _, [%0];" :: "r"(addr) : "memory")
#define MBAR_EXPECT_TX(addr, bytes) \
    asm volatile("mbarrier.arrive.expect_tx.shared.b64 _, [%0], %1;" :: "r"(addr), "r"(bytes) : "memory")
#define MBAR_WAIT(addr, parity) do { \
    uint32_t _m = (addr), _p = (parity), _d; \
    asm volatile("{\n\t.reg .pred p;\n\tmbarrier.try_wait.parity.acquire.cta.shared::cta.b64 p, [%1], %2;\n\tselp.b32 %0, 1, 0, p;\n\t}" \
        : "=r"(_d) : "r"(_m), "r"(_p) : "memory"); \
    if (!_d) { \
        asm volatile("{\n\t.reg .pred P1;\n\tWL_%=:\n\tmbarrier.try_wait.parity.acquire.cta.shared::cta.b64 P1, [%0], %1, 0x989680;\n\t@P1 bra.uni WD_%=;\n\tbra.uni WL_%=;\n\tWD_%=:\n\t}" \
            :: "r"(_m), "r"(_p) : "memory"); \
    } \
} while (0)

__device__ __forceinline__ void tma_bulk(uint32_t dst, const void* src, uint32_t bytes, uint32_t mbar) {
    asm volatile("cp.async.bulk.shared::cluster.global.mbarrier::complete_tx::bytes [%0], [%1], %2, [%3];"
                 :: "r"(dst), "l"(src), "r"(bytes), "r"(mbar) : "memory");
}

#define LDSM4(r0, r1, r2, r3, addr) \
    asm volatile("ldmatrix.sync.aligned.m8n8.x4.shared.b16 {%0,%1,%2,%3}, [%4];" \
                 : "=r"(r0), "=r"(r1), "=r"(r2), "=r"(r3) : "r"(addr))

#define MMA_BF(c, a, b0, b1) \
    asm volatile("mma.sync.aligned.m16n8k16.row.col.f32.bf16.bf16.f32 " \
                 "{%0,%1,%2,%3}, {%4,%5,%6,%7}, {%8,%9}, {%0,%1,%2,%3};\n" \
                 : "+f"((c)[0]), "+f"((c)[1]), "+f"((c)[2]), "+f"((c)[3]) \
                 : "r"((a)[0]), "r"((a)[1]), "r"((a)[2]), "r"((a)[3]), "r"(b0), "r"(b1))

#define MMA_FP(c, a, b0, b1) \
    asm volatile("mma.sync.aligned.m16n8k16.row.col.f32.f16.f16.f32 " \
                 "{%0,%1,%2,%3}, {%4,%5,%6,%7}, {%8,%9}, {%0,%1,%2,%3};\n" \
                 : "+f"((c)[0]), "+f"((c)[1]), "+f"((c)[2]), "+f"((c)[3]) \
                 : "r"((a)[0]), "r"((a)[1]), "r"((a)[2]), "r"((a)[3]), "r"(b0), "r"(b1))

// ---------------- mixing: 4 channels per thread ----------------
__global__ void mix_split(const float* __restrict__ x, const float* __restrict__ mask,
                          const float* __restrict__ mr, const float* __restrict__ mw,
                          const float* __restrict__ mk, const float* __restrict__ mv,
                          const float* __restrict__ ma, const float* __restrict__ mg)
{
    size_t p = (size_t)blockIdx.x * blockDim.x + threadIdx.x;
    if (p >= BTC / 4) return;
    int cq = (int)(p % (Cn / 4));
    int c = cq * 4;
    size_t bt = p / (Cn / 4);
    int t = (int)(bt % Tn);
    float m = mask[bt];
    float4 xc = *(const float4*)&x[bt * Cn + c];
    float x0 = xc.x * m, x1 = xc.y * m, x2 = xc.z * m, x3 = xc.w * m;
    float p0 = 0.f, p1 = 0.f, p2 = 0.f, p3 = 0.f;
    if (t > 0) {
        float mp = mask[bt - 1];
        float4 xp = *(const float4*)&x[(bt - 1) * Cn + c];
        p0 = xp.x * mp; p1 = xp.y * mp; p2 = xp.z * mp; p3 = xp.w * mp;
    }
    float d0 = p0 - x0, d1 = p1 - x1, d2 = p2 - x2, d3 = p3 - x3;

    int mb = (int)(bt >> 7), r = (int)(bt & 127), kt = c >> 5, cc = c & 31;
    size_t ti = tile_idx8(mb, kt, r, cc);

    {
        float4 ck = *(const float4*)&mk[c];
        split_store4(g_xkt, ti, 4096, x0 + d0 * ck.x, x1 + d1 * ck.y, x2 + d2 * ck.z, x3 + d3 * ck.w);
    }
    {
        float4 cv = *(const float4*)&mv[c];
        split_store4(g_xvt, ti, 4096, x0 + d0 * cv.x, x1 + d1 * cv.y, x2 + d2 * cv.z, x3 + d3 * cv.w);
    }
    {
        float4 cw = *(const float4*)&mw[c];
        split_store4(g_xwt, ti, 4096, x0 + d0 * cw.x, x1 + d1 * cw.y, x2 + d2 * cw.z, x3 + d3 * cw.w);
    }
    {
        float4 ca = *(const float4*)&ma[c];
        split_store4(g_xat, ti, 4096, x0 + d0 * ca.x, x1 + d1 * ca.y, x2 + d2 * ca.z, x3 + d3 * ca.w);
    }
    {
        float4 cg = *(const float4*)&mg[c];
        split_store4(g_xgt, ti, 4096, x0 + d0 * cg.x, x1 + d1 * cg.y, x2 + d2 * cg.z, x3 + d3 * cg.w);
    }
    {
        float4 cr = *(const float4*)&mr[c];
        size_t ti4 = tile_idx4(mb, kt, r, cc);
        __half2 h01 = __floats2half2_rn(x0 + d0 * cr.x, x1 + d1 * cr.y);
        __half2 h23 = __floats2half2_rn(x2 + d2 * cr.z, x3 + d3 * cr.w);
        *(uint2*)&g_xrt16[ti4] = make_uint2(*(uint32_t*)&h01, *(uint32_t*)&h23);
    }
}

// ---------------- weight conversions ----------------
__global__ void conv_wt4(const float* __restrict__ Wr, const float* __restrict__ Wk,
                         const float* __restrict__ Wv, const float* __restrict__ Wo)
{
    size_t p = (size_t)blockIdx.x * blockDim.x + threadIdx.x;
    if (p >= (size_t)Cn * Cn / 4) return;
    int z = blockIdx.y;
    int n = (int)(p / (Cn / 4)), k = (int)(p % (Cn / 4)) * 4;
    if (z == 1 || z == 2) {
        const float* src = (z == 1) ? Wk : Wv;
        float4 v = *(const float4*)&src[(size_t)n * Cn + k];
        split_store4(g_Wt[z - 1], tile_idx8(n >> 7, k >> 5, n & 127, k & 31), 4096,
                     v.x, v.y, v.z, v.w);
    } else {
        const float* src = (z == 0) ? Wr : Wo;
        __half* dst = (z == 0) ? g_Wr16 : g_Wo16;
        float4 v = *(const float4*)&src[(size_t)n * Cn + k];
        __half2 h01 = __floats2half2_rn(v.x, v.y);
        __half2 h23 = __floats2half2_rn(v.z, v.w);
        *(uint2*)&dst[tile_idx4(n >> 7, k >> 5, n & 127, k & 31)] =
            make_uint2(*(uint32_t*)&h01, *(uint32_t*)&h23);
    }
}

__global__ void tsplit_all(const float* __restrict__ w1, const float* __restrict__ a1,
                           const float* __restrict__ v1, const float* __restrict__ g1,
                           const float* __restrict__ w2, const float* __restrict__ a2,
                           const float* __restrict__ v2, const float* __restrict__ g2)
{
    int i = blockIdx.x * blockDim.x + threadIdx.x;
    if (i >= KP * Cn) return;
    int z = blockIdx.y;
    if (z < 4) {
        const float* in = (z == 0) ? w1 : (z == 1) ? a1 : (z == 2) ? v1 : g1;
        int nd = (z == 2) ? 64 : (z == 3) ? 128 : 96;
        int n = i / Cn, k = i % Cn;
        float v = (n < nd) ? in[(size_t)k * nd + n] : 0.f;
        split_store(g_w1bt[z], tile_idx8(0, k >> 5, n, k & 31), 4096, v);
    } else {
        int zz = z - 4;
        const float* in = (zz == 0) ? w2 : (zz == 1) ? a2 : (zz == 2) ? v2 : g2;
        int nd = (zz == 2) ? 64 : (zz == 3) ? 128 : 96;
        int n = i / KP, k = i % KP;
        float v = (k < nd) ? in[(size_t)k * Cn + n] : 0.f;
        split_store(g_w2t[zz], (size_t)n * (2 * KP) + k, KP, v);
    }
}

// ---------------- merged bulk-TMA GEMM ----------------
// z 0..1: k/v (bf16 3-term, 3 stages x 32KB); z 2..5: mlp1 (bn==0, bf16 3-term);
// z 6: r (fp16 single-segment, 6 stages x 16KB)
__global__ __launch_bounds__(256, 2)
void bgemm3()
{
    const int bn = blockIdx.x, bm = blockIdx.y, z = blockIdx.z;
    if (z >= 2 && z < 6 && bn != 0) return;

    extern __shared__ __align__(1024) char smem[];
    const uint32_t sb = smem_u32(smem);
    const int tid = threadIdx.x, w = tid >> 5, lane = tid & 31;
    const int wm = (w & 3) * 32, wn = (w >> 2) * 64;

    const uint32_t FULL = sb;
    const uint32_t EMPTY = sb + 64;
    const uint32_t ST = sb + 1024;

    if (tid == 0) {
#pragma unroll
        for (int s = 0; s < 6; s++) { MBAR_INIT(FULL + 8 * s, 1); MBAR_INIT(EMPTY + 8 * s, 8); }
    }
    __syncthreads();

    float acc[2][8][4];
#pragma unroll
    for (int mi = 0; mi < 2; mi++)
#pragma unroll
        for (int ni = 0; ni < 8; ni++)
#pragma unroll
            for (int q = 0; q < 4; q++) acc[mi][ni][q] = 0.f;

    if (z == 6) {
        const __half* A = g_xrt16;
        const __half* Bw = g_Wr16;
        if (tid == 0) {
#pragma unroll
            for (int t = 0; t < 5; t++) {
                MBAR_EXPECT_TX(FULL + 8 * t, 16384u);
                tma_bulk(ST + t * 16384,        A  + ((size_t)(bm * 64 + t)) * 4096, 8192u, FULL + 8 * t);
                tma_bulk(ST + t * 16384 + 8192, Bw + ((size_t)(bn * 64 + t)) * 4096, 8192u, FULL + 8 * t);
            }
        }
        for (int t = 0; t < 64; t++) {
            int s = t % 6;
            if (tid == 0 && t + 5 < 64) {
                int tp = t + 5, sp = tp % 6, up = tp / 6;
                if (up >= 1) MBAR_WAIT(EMPTY + 8 * sp, (up - 1) & 1);
                MBAR_EXPECT_TX(FULL + 8 * sp, 16384u);
                tma_bulk(ST + sp * 16384,        A  + ((size_t)(bm * 64 + tp)) * 4096, 8192u, FULL + 8 * sp);
                tma_bulk(ST + sp * 16384 + 8192, Bw + ((size_t)(bn * 64 + tp)) * 4096, 8192u, FULL + 8 * sp);
            }
            MBAR_WAIT(FULL + 8 * s, (t / 6) & 1);
            const uint32_t st = ST + s * 16384;
#pragma unroll
            for (int kk = 0; kk < 32; kk += 16) {
                uint32_t af[2][4];
#pragma unroll
                for (int mi = 0; mi < 2; mi++) {
                    int rr = wm + mi * 16 + (lane & 15);
                    int c8 = (kk >> 3) + (lane >> 4);
                    int slot = c8 ^ ((rr >> 1) & 3);
                    LDSM4(af[mi][0], af[mi][1], af[mi][2], af[mi][3],
                          st + (uint32_t)(rr * 64 + slot * 16));
                }
#pragma unroll
                for (int n2 = 0; n2 < 4; n2++) {
                    int rb = wn + n2 * 16 + (lane & 7) + ((lane & 16) ? 8 : 0);
                    int c8 = (kk >> 3) + ((lane & 8) ? 1 : 0);
                    int slot = c8 ^ ((rb >> 1) & 3);
                    uint32_t bq[4];
                    LDSM4(bq[0], bq[1], bq[2], bq[3],
                          st + 8192 + (uint32_t)(rb * 64 + slot * 16));
#pragma unroll
                    for (int mi = 0; mi < 2; mi++) {
                        MMA_FP(acc[mi][2 * n2],     af[mi], bq[0], bq[1]);
                        MMA_FP(acc[mi][2 * n2 + 1], af[mi], bq[2], bq[3]);
                    }
                }
            }
            if (lane == 0) MBAR_ARRIVE(EMPTY + 8 * s);
        }
#pragma unroll
        for (int mi = 0; mi < 2; mi++)
#pragma unroll
            for (int ni = 0; ni < 8; ni++) {
                int row = bm * 128 + wm + mi * 16 + (lane >> 2);
                int col = bn * 128 + wn + ni * 8 + (lane & 3) * 2;
                float* c = acc[mi][ni];
                g_r[(size_t)row * Cn + col]           = c[0];
                g_r[(size_t)row * Cn + col + 1]       = c[1];
                g_r[(size_t)(row + 8) * Cn + col]     = c[2];
                g_r[(size_t)(row + 8) * Cn + col + 1] = c[3];
            }
        return;
    }

    const bf16* A;
    const bf16* Bw;
    if (z < 2) {
        A = (z == 0) ? g_xkt : g_xvt;
        Bw = g_Wt[z];
    } else {
        A = (z == 2) ? g_xwt : (z == 3) ? g_xat : (z == 4) ? g_xvt : g_xgt;
        Bw = g_w1bt[z - 2];
    }

    if (tid == 0) {
#pragma unroll
        for (int t = 0; t < 2; t++) {
            MBAR_EXPECT_TX(FULL + 8 * t, 32768u);
            tma_bulk(ST + t * 32768,         A  + ((size_t)(bm * 64 + t)) * 8192, 16384u, FULL + 8 * t);
            tma_bulk(ST + t * 32768 + 16384, Bw + ((size_t)(bn * 64 + t)) * 8192, 16384u, FULL + 8 * t);
        }
    }

    for (int t = 0; t < 64; t++) {
        int s = t % 3;
        if (tid == 0 && t + 2 < 64) {
            int tp = t + 2, sp = tp % 3, up = tp / 3;
            if (up >= 1) MBAR_WAIT(EMPTY + 8 * sp, (up - 1) & 1);
            MBAR_EXPECT_TX(FULL + 8 * sp, 32768u);
            tma_bulk(ST + sp * 32768,         A  + ((size_t)(bm * 64 + tp)) * 8192, 16384u, FULL + 8 * sp);
            tma_bulk(ST + sp * 32768 + 16384, Bw + ((size_t)(bn * 64 + tp)) * 8192, 16384u, FULL + 8 * sp);
        }
        MBAR_WAIT(FULL + 8 * s, (t / 3) & 1);
        const uint32_t st = ST + s * 32768;

#pragma unroll
        for (int kk = 0; kk < 32; kk += 16) {
            uint32_t ah[2][4], al[2][4];
#pragma unroll
            for (int mi = 0; mi < 2; mi++) {
                int rr = wm + mi * 16 + (lane & 15);
                int c8 = (kk >> 3) + (lane >> 4);
                int slot = c8 ^ ((rr >> 1) & 3);
                uint32_t ad = st + (uint32_t)(rr * 64 + slot * 16);
                LDSM4(ah[mi][0], ah[mi][1], ah[mi][2], ah[mi][3], ad);
                LDSM4(al[mi][0], al[mi][1], al[mi][2], al[mi][3], ad + 8192);
            }
#pragma unroll
            for (int n2 = 0; n2 < 4; n2++) {
                int rb = wn + n2 * 16 + (lane & 7) + ((lane & 16) ? 8 : 0);
                int c8 = (kk >> 3) + ((lane & 8) ? 1 : 0);
                int slot = c8 ^ ((rb >> 1) & 3);
                uint32_t bd = st + 16384 + (uint32_t)(rb * 64 + slot * 16);
                uint32_t bh[4], bl[4];
                LDSM4(bh[0], bh[1], bh[2], bh[3], bd);
                LDSM4(bl[0], bl[1], bl[2], bl[3], bd + 8192);
#pragma unroll
                for (int mi = 0; mi < 2; mi++) {
                    MMA_BF(acc[mi][2 * n2],     ah[mi], bh[0], bh[1]);
                    MMA_BF(acc[mi][2 * n2 + 1], ah[mi], bh[2], bh[3]);
                    MMA_BF(acc[mi][2 * n2],     al[mi], bh[0], bh[1]);
                    MMA_BF(acc[mi][2 * n2 + 1], al[mi], bh[2], bh[3]);
                    MMA_BF(acc[mi][2 * n2],     ah[mi], bl[0], bl[1]);
                    MMA_BF(acc[mi][2 * n2 + 1], ah[mi], bl[2], bl[3]);
                }
            }
        }
        if (lane == 0) MBAR_ARRIVE(EMPTY + 8 * s);
    }

#pragma unroll
    for (int mi = 0; mi < 2; mi++)
#pragma unroll
        for (int ni = 0; ni < 8; ni++) {
            int row = bm * 128 + wm + mi * 16 + (lane >> 2);
            int col = bn * 128 + wn + ni * 8 + (lane & 3) * 2;
            float* c = acc[mi][ni];
            if (z < 2) {
                float* C = (z == 0) ? g_k : g_v;
                C[(size_t)row * Cn + col]           = c[0];
                C[(size_t)row * Cn + col + 1]       = c[1];
                C[(size_t)(row + 8) * Cn + col]     = c[2];
                C[(size_t)(row + 8) * Cn + col + 1] = c[3];
            } else {
                bf16* hid = g_hid4[z - 2];
                auto act = [&](float v) -> float {
                    if (z == 2) return tanhf(v);
                    if (z == 5) return 1.f / (1.f + expf(-v));
                    return v;
                };
                split_store(hid, (size_t)row * 256 + col,           KP, act(c[0]));
                split_store(hid, (size_t)row * 256 + col + 1,       KP, act(c[1]));
                split_store(hid, (size_t)(row + 8) * 256 + col,     KP, act(c[2]));
                split_store(hid, (size_t)(row + 8) * 256 + col + 1, KP, act(c[3]));
            }
        }
}

// ---------------- bulk-TMA fp16 single GEMM (out-proj) ----------------
__global__ __launch_bounds__(256, 2)
void bgemm1(const __half* __restrict__ A, const __half* __restrict__ Bw,
            float* __restrict__ C)
{
    extern __shared__ __align__(1024) char smem[];
    const uint32_t sb = smem_u32(smem);
    const int tid = threadIdx.x, w = tid >> 5, lane = tid & 31;
    const int bn = blockIdx.x, bm = blockIdx.y;
    const int wm = (w & 3) * 32, wn = (w >> 2) * 64;

    const uint32_t FULL = sb;
    const uint32_t EMPTY = sb + 64;
    const uint32_t ST = sb + 1024;

    if (tid == 0) {
#pragma unroll
        for (int s = 0; s < 6; s++) { MBAR_INIT(FULL + 8 * s, 1); MBAR_INIT(EMPTY + 8 * s, 8); }
    }
    __syncthreads();

    if (tid == 0) {
#pragma unroll
        for (int t = 0; t < 5; t++) {
            MBAR_EXPECT_TX(FULL + 8 * t, 16384u);
            tma_bulk(ST + t * 16384,        A  + ((size_t)(bm * 64 + t)) * 4096, 8192u, FULL + 8 * t);
            tma_bulk(ST + t * 16384 + 8192, Bw + ((size_t)(bn * 64 + t)) * 4096, 8192u, FULL + 8 * t);
        }
    }

    float acc[2][8][4];
#pragma unroll
    for (int mi = 0; mi < 2; mi++)
#pragma unroll
        for (int ni = 0; ni < 8; ni++)
#pragma unroll
            for (int q = 0; q < 4; q++) acc[mi][ni][q] = 0.f;

    for (int t = 0; t < 64; t++) {
        int s = t % 6;
        if (tid == 0 && t + 5 < 64) {
            int tp = t + 5, sp = tp % 6, up = tp / 6;
            if (up >= 1) MBAR_WAIT(EMPTY + 8 * sp, (up - 1) & 1);
            MBAR_EXPECT_TX(FULL + 8 * sp, 16384u);
            tma_bulk(ST + sp * 16384,        A  + ((size_t)(bm * 64 + tp)) * 4096, 8192u, FULL + 8 * sp);
            tma_bulk(ST + sp * 16384 + 8192, Bw + ((size_t)(bn * 64 + tp)) * 4096, 8192u, FULL + 8 * sp);
        }
        MBAR_WAIT(FULL + 8 * s, (t / 6) & 1);
        const uint32_t st = ST + s * 16384;

#pragma unroll
        for (int kk = 0; kk < 32; kk += 16) {
            uint32_t af[2][4];
#pragma unroll
            for (int mi = 0; mi < 2; mi++) {
                int rr = wm + mi * 16 + (lane & 15);
                int c8 = (kk >> 3) + (lane >> 4);
                int slot = c8 ^ ((rr >> 1) & 3);
                LDSM4(af[mi][0], af[mi][1], af[mi][2], af[mi][3],
                      st + (uint32_t)(rr * 64 + slot * 16));
            }
#pragma unroll
            for (int n2 = 0; n2 < 4; n2++) {
                int rb = wn + n2 * 16 + (lane & 7) + ((lane & 16) ? 8 : 0);
                int c8 = (kk >> 3) + ((lane & 8) ? 1 : 0);
                int slot = c8 ^ ((rb >> 1) & 3);
                uint32_t bq[4];
                LDSM4(bq[0], bq[1], bq[2], bq[3],
                      st + 8192 + (uint32_t)(rb * 64 + slot * 16));
#pragma unroll
                for (int mi = 0; mi < 2; mi++) {
                    MMA_FP(acc[mi][2 * n2],     af[mi], bq[0], bq[1]);
                    MMA_FP(acc[mi][2 * n2 + 1], af[mi], bq[2], bq[3]);
                }
            }
        }
        if (lane == 0) MBAR_ARRIVE(EMPTY + 8 * s);
    }

#pragma unroll
    for (int mi = 0; mi < 2; mi++)
#pragma unroll
        for (int ni = 0; ni < 8; ni++) {
            int row = bm * 128 + wm + mi * 16 + (lane >> 2);
            int col = bn * 128 + wn + ni * 8 + (lane & 3) * 2;
            float* c = acc[mi][ni];
            C[(size_t)row * Cn + col]           = c[0];
            C[(size_t)row * Cn + col + 1]       = c[1];
            C[(size_t)(row + 8) * Cn + col]     = c[2];
            C[(size_t)(row + 8) * Cn + col + 1] = c[3];
        }
}

// ---------------- mma.sync split-bf16 GEMM for MLP2 (skip zero-padded K) ----------------
__global__ __launch_bounds__(256, 2)
void hgemm2(const float* __restrict__ b0, const float* __restrict__ b1,
            const float* __restrict__ b2)
{
    constexpr int SSZ = 128 * 40;
    extern __shared__ bf16 sh[];
    bf16* As = sh;
    bf16* Bs = sh + 3 * SSZ;

    const int tid = threadIdx.x;
    const int z = blockIdx.z;
    const int bm = blockIdx.y * 128, bn = blockIdx.x * 128;
    const int w = tid >> 5, lane = tid & 31;
    const int wm = (w & 3) * 32, wn = (w >> 2) * 64;

    const bf16* A = g_hid4[z];
    const bf16* Bw = g_w2t[z];
    // actual hidden dims: w=96, a=96, v=64, g=128 -> tiles per segment
    const int tps = (z == 2) ? 2 : (z == 3) ? 4 : 3;
    const int KT = 3 * tps;

    float acc[2][8][4];
#pragma unroll
    for (int mi = 0; mi < 2; mi++)
#pragma unroll
        for (int ni = 0; ni < 8; ni++)
#pragma unroll
            for (int q = 0; q < 4; q++) acc[mi][ni][q] = 0.f;

    auto loadtile = [&](int stage, int t) {
        int seg = (t >= 2 * tps) ? 2 : (t >= tps) ? 1 : 0;
        int kk = (t - seg * tps) * 32;
        int aoff = (seg == 1 ? 128 : 0) + kk;
        int boff = (seg == 2 ? 128 : 0) + kk;
        bf16* as = As + stage * SSZ;
        bf16* bs = Bs + stage * SSZ;
#pragma unroll
        for (int c = 0; c < 2; c++) {
            int ch = tid + c * 256;
            int row = ch >> 2, col = ch & 3;
            unsigned sa = (unsigned)__cvta_generic_to_shared(&as[row * 40 + col * 8]);
            const void* ga = &A[(size_t)(bm + row) * 256 + aoff + col * 8];
            asm volatile("cp.async.cg.shared.global [%0], [%1], 16;\n" :: "r"(sa), "l"(ga));
            unsigned sb2 = (unsigned)__cvta_generic_to_shared(&bs[row * 40 + col * 8]);
            const void* gb = &Bw[(size_t)(bn + row) * 256 + boff + col * 8];
            asm volatile("cp.async.cg.shared.global [%0], [%1], 16;\n" :: "r"(sb2), "l"(gb));
        }
        asm volatile("cp.async.commit_group;\n" ::: "memory");
    };

    loadtile(0, 0);
    loadtile(1, 1);

    const int arow = wm + (lane & 15);
    const int acolo = (lane >> 4) << 3;
    const int brow = (lane & 7) + ((lane & 16) ? 8 : 0);
    const int bcolo = (lane & 8) ? 8 : 0;

    for (int t = 0; t < KT; t++) {
        if (t + 1 < KT) {
            asm volatile("cp.async.wait_group 1;\n" ::: "memory");
        } else {
            asm volatile("cp.async.wait_group 0;\n" ::: "memory");
        }
        __syncthreads();
        if (t + 2 < KT) loadtile((t + 2) % 3, t + 2);

        const bf16* as = As + (t % 3) * SSZ;
        const bf16* bs = Bs + (t % 3) * SSZ;
        unsigned abase = (unsigned)__cvta_generic_to_shared(as);
        unsigned bbase = (unsigned)__cvta_generic_to_shared(bs);

#pragma unroll
        for (int kk = 0; kk < 32; kk += 16) {
            uint32_t af[2][4];
#pragma unroll
            for (int mi = 0; mi < 2; mi++) {
                unsigned aaddr = abase + (unsigned)(((arow + mi * 16) * 40 + kk + acolo) * 2);
                LDSM4(af[mi][0], af[mi][1], af[mi][2], af[mi][3], aaddr);
            }
            uint32_t bq[4][4];
#pragma unroll
            for (int n2 = 0; n2 < 4; n2++) {
                unsigned baddr = bbase + (unsigned)(((wn + n2 * 16 + brow) * 40 + kk + bcolo) * 2);
                LDSM4(bq[n2][0], bq[n2][1], bq[n2][2], bq[n2][3], baddr);
            }
#pragma unroll
            for (int n2 = 0; n2 < 4; n2++) {
#pragma unroll
                for (int mi = 0; mi < 2; mi++) {
                    MMA_BF(acc[mi][2 * n2],     af[mi], bq[n2][0], bq[n2][1]);
                    MMA_BF(acc[mi][2 * n2 + 1], af[mi], bq[n2][2], bq[n2][3]);
                }
            }
        }
        __syncthreads();
    }

#pragma unroll
    for (int mi = 0; mi < 2; mi++)
#pragma unroll
        for (int ni = 0; ni < 8; ni++) {
            int row = bm + wm + mi * 16 + (lane >> 2);
            int col = bn + wn + ni * 8 + (lane & 3) * 2;
            float* c = acc[mi][ni];
            float* dst = (z == 0) ? g_wdec : (z == 1) ? g_a : (z == 2) ? g_vg : g_g;
            auto epi = [&](float v, int n) -> float {
                if (z == 0) return expf(-0.60653066f / (1.f + expf(-(b0[n] + v))));
                if (z == 1) return 1.f / (1.f + expf(-(b1[n] + v)));
                if (z == 2) return 1.f / (1.f + expf(-(b2[n] + v)));
                return v;
            };
            dst[(size_t)row * Cn + col]           = epi(c[0], col);
            dst[(size_t)row * Cn + col + 1]       = epi(c[1], col + 1);
            dst[(size_t)(row + 8) * Cn + col]     = epi(c[2], col);
            dst[(size_t)(row + 8) * Cn + col + 1] = epi(c[3], col + 1);
        }
}

// ---------------- fused: v-combine + kk-normalize + k-update ----------------
__global__ __launch_bounds__(256)
void kkv_fused(const float* __restrict__ vf, const float* __restrict__ mask,
               const float* __restrict__ kkw, const float* __restrict__ kaw)
{
    const int warp = threadIdx.x >> 5, lane = threadIdx.x & 31;
    const int gid = blockIdx.x * 8 + warp;
    const int h = gid & (Hn - 1);
    const int bt = gid >> 5;
    size_t base = (size_t)gid * 64;
    int c0 = h * 64 + lane, c1 = c0 + 32;
    float m = mask[bt];

    float v0v = g_v[base + lane], v1v = g_v[base + lane + 32];
    float gt0 = g_vg[base + lane], gt1 = g_vg[base + lane + 32];
    v0v = (v0v + (vf[base + lane] - v0v) * gt0) * m;
    v1v = (v1v + (vf[base + lane + 32] - v1v) * gt1) * m;
    g_v[base + lane] = v0v;
    g_v[base + lane + 32] = v1v;

    float k0v = g_k[base + lane], k1v = g_k[base + lane + 32];
    float kk0 = k0v * kkw[c0], kk1 = k1v * kkw[c1];
    float ss = kk0 * kk0 + kk1 * kk1;
#pragma unroll
    for (int off = 16; off > 0; off >>= 1) ss += __shfl_xor_sync(0xffffffffu, ss, off);
    float inv = 1.f / fmaxf(sqrtf(ss), 1e-12f);
    float a0v = g_a[base + lane], a1v = g_a[base + lane + 32];
    g_nkk[base + lane]      = -kk0 * inv;
    g_nkk[base + lane + 32] = -kk1 * inv;
    g_ab[base + lane]       = kk0 * inv * a0v;
    g_ab[base + lane + 32]  = kk1 * inv * a1v;
    g_knew[base + lane]      = k0v * (1.f + (a0v - 1.f) * kaw[c0]);
    g_knew[base + lane + 32] = k1v * (1.f + (a1v - 1.f) * kaw[c1]);
}

// ---------------- RWKV-7 scan: 128 threads, packed f32x2, prefetch depth 2 ----------------
__device__ __forceinline__ void scan_step(float* sb, uint64_t* S2, int tid, int j, int half,
                                          size_t ybase)
{
    const uint64_t zero2 = pkf2(0.f, 0.f);
    const uint64_t* rv2 = (const uint64_t*)(sb + half * 32);
    const uint64_t* wv2 = (const uint64_t*)(sb + 64 + half * 32);
    const uint64_t* kv2 = (const uint64_t*)(sb + 128 + half * 32);
    const uint64_t* av2 = (const uint64_t*)(sb + 256 + half * 32);
    const uint64_t* bv2 = (const uint64_t*)(sb + 320 + half * 32);

    uint64_t saA = zero2, saB = zero2;
#pragma unroll
    for (int ii = 0; ii < 16; ii += 2) {
        FMA2(saA, S2[ii],     av2[ii],     saA);
        FMA2(saB, S2[ii + 1], av2[ii + 1], saB);
    }
    float s0, s1, s2, s3;
    upkf2(saA, s0, s1); upkf2(saB, s2, s3);
    float sa = (s0 + s1) + (s2 + s3);
    sa += __shfl_xor_sync(0xffffffffu, sa, 1);

    float vj = sb[192 + j];
    uint64_t vj2 = pkf2(vj, vj);
    uint64_t sa2 = pkf2(sa, sa);
    uint64_t yA = zero2, yB = zero2;
#pragma unroll
    for (int ii = 0; ii < 16; ii += 2) {
        uint64_t t0, t1;
        MUL2(t0, vj2, kv2[ii]);
        MUL2(t1, vj2, kv2[ii + 1]);
        FMA2(t0, sa2, bv2[ii],     t0);
        FMA2(t1, sa2, bv2[ii + 1], t1);
        FMA2(S2[ii],     S2[ii],     wv2[ii],     t0);
        FMA2(S2[ii + 1], S2[ii + 1], wv2[ii + 1], t1);
        FMA2(yA, S2[ii],     rv2[ii],     yA);
        FMA2(yB, S2[ii + 1], rv2[ii + 1], yB);
    }
    float y0, y1, y2, y3;
    upkf2(yA, y0, y1); upkf2(yB, y2, y3);
    float y = (y0 + y1) + (y2 + y3);
    y += __shfl_xor_sync(0xffffffffu, y, 1);
    if (!half) g_y[ybase + j] = y;
}

__global__ __launch_bounds__(128)
void scan_kernel()
{
    const int bh = blockIdx.x;
    const int b = bh >> 5, h = bh & 31;
    const int tid = threadIdx.x;
    const int j = tid >> 1, half = tid & 1;
    size_t base = (size_t)b * Tn * Cn + h * 64;

    uint64_t S2[16];
    const uint64_t zero2 = pkf2(0.f, 0.f);
#pragma unroll
    for (int i = 0; i < 16; i++) S2[i] = zero2;

    __shared__ float sm[2][384];

    const float* gsrc0;
    const float* gsrc1;
    const float* gsrc2;
    {
        const float* tbl[6] = {g_r, g_wdec, g_knew, g_v, g_nkk, g_ab};
        int l0 = tid, l1 = tid + 128, l2 = tid + 256;
        gsrc0 = tbl[l0 >> 6] + base + (l0 & 63);
        gsrc1 = tbl[l1 >> 6] + base + (l1 & 63);
        gsrc2 = tbl[l2 >> 6] + base + (l2 & 63);
    }
    float fa0 = gsrc0[0],  fa1 = gsrc1[0],  fa2 = gsrc2[0];
    float fb0 = gsrc0[Cn], fb1 = gsrc1[Cn], fb2 = gsrc2[Cn];
    gsrc0 += 2 * Cn; gsrc1 += 2 * Cn; gsrc2 += 2 * Cn;

    for (int t = 0; t < Tn; t += 2) {
        {
            float* sb = sm[0];
            sb[tid] = fa0; sb[tid + 128] = fa1; sb[tid + 256] = fa2;
            __syncthreads();
            if (t + 2 < Tn) {
                fa0 = gsrc0[0]; fa1 = gsrc1[0]; fa2 = gsrc2[0];
                gsrc0 += Cn; gsrc1 += Cn; gsrc2 += Cn;
            }
            scan_step(sb, S2, tid, j, half, base + (size_t)t * Cn);
        }
        {
            float* sb = sm[1];
            sb[tid] = fb0; sb[tid + 128] = fb1; sb[tid + 256] = fb2;
            __syncthreads();
            if (t + 3 < Tn) {
                fb0 = gsrc0[0]; fb1 = gsrc1[0]; fb2 = gsrc2[0];
                gsrc0 += Cn; gsrc1 += Cn; gsrc2 += Cn;
            }
            scan_step(sb, S2, tid, j, half, base + (size_t)(t + 1) * Cn);
        }
    }
}

// ---------------- groupnorm + rk bonus + gate -> fp16 tiled ----------------
__global__ __launch_bounds__(128)
void postln_kernel(const float* __restrict__ rkw, const float* __restrict__ lnw,
                   const float* __restrict__ lnb)
{
    const int warp = threadIdx.x >> 5, lane = threadIdx.x & 31;
    const int gid = blockIdx.x * 4 + warp;
    const int h = gid & (Hn - 1);
    const int bt = gid >> 5;
    size_t base = (size_t)gid * 64;
    int c0 = h * 64 + lane, c1 = c0 + 32;

    float y0 = g_y[base + lane], y1 = g_y[base + lane + 32];
    float s = y0 + y1;
#pragma unroll
    for (int off = 16; off > 0; off >>= 1) s += __shfl_xor_sync(0xffffffffu, s, off);
    float mu = s * (1.f / 64.f);
    float d0 = y0 - mu, d1 = y1 - mu;
    float vs = d0 * d0 + d1 * d1;
#pragma unroll
    for (int off = 16; off > 0; off >>= 1) vs += __shfl_xor_sync(0xffffffffu, vs, off);
    float inv = rsqrtf(vs * (1.f / 64.f) + LN_EPS);

    float rk = g_r[base + lane] * g_knew[base + lane] * rkw[c0]
             + g_r[base + lane + 32] * g_knew[base + lane + 32] * rkw[c1];
#pragma unroll
    for (int off = 16; off > 0; off >>= 1) rk += __shfl_xor_sync(0xffffffffu, rk, off);

    float yn0 = d0 * inv * lnw[c0] + lnb[c0];
    float yn1 = d1 * inv * lnw[c1] + lnb[c1];
    float o0 = (yn0 + rk * g_v[base + lane])      * g_g[base + lane];
    float o1 = (yn1 + rk * g_v[base + lane + 32]) * g_g[base + lane + 32];

    int mb = bt >> 7, r = bt & 127;
    g_ygt[tile_idx4(mb, c0 >> 5, r, c0 & 31)] = __float2half(o0);
    g_ygt[tile_idx4(mb, c1 >> 5, r, c1 & 31)] = __float2half(o1);
}

// ---------------- host ----------------
template<typename T> static T* sym(const void* s) { void* p = nullptr; cudaGetSymbolAddress(&p, s); return (T*)p; }

extern "C" void kernel_launch(void* const* d_in, const int* in_sizes, int n_in,
                              void* d_out, int out_size)
{
    const float* x    = (const float*)d_in[0];
    const float* mask = (const float*)d_in[1];
    const float* vf   = (const float*)d_in[2];
    const float* x_r  = (const float*)d_in[3];
    const float* x_w  = (const float*)d_in[4];
    const float* x_k  = (const float*)d_in[5];
    const float* x_v  = (const float*)d_in[6];
    const float* x_a  = (const float*)d_in[7];
    const float* x_g  = (const float*)d_in[8];
    const float* w0   = (const float*)d_in[9];
    const float* w1   = (const float*)d_in[10];
    const float* w2   = (const float*)d_in[11];
    const float* a0   = (const float*)d_in[12];
    const float* a1   = (const float*)d_in[13];
    const float* a2   = (const float*)d_in[14];
    const float* v0   = (const float*)d_in[15];
    const float* v1   = (const float*)d_in[16];
    const float* v2   = (const float*)d_in[17];
    const float* g1   = (const float*)d_in[18];
    const float* g2   = (const float*)d_in[19];
    const float* k_k  = (const float*)d_in[20];
    const float* k_a  = (const float*)d_in[21];
    const float* r_k  = (const float*)d_in[22];
    const float* W_r  = (const float*)d_in[23];
    const float* W_k  = (const float*)d_in[24];
    const float* W_v  = (const float*)d_in[25];
    const float* W_o  = (const float*)d_in[26];
    const float* ln_w = (const float*)d_in[27];
    const float* ln_b = (const float*)d_in[28];

    __half* p_Wo16  = sym<__half>(g_Wo16);
    __half* p_ygt   = sym<__half>(g_ygt);

    float* out = (float*)d_out;

    const unsigned EW4 = (unsigned)((BTC / 4 + 255) / 256);
    const unsigned WW4 = (unsigned)(((size_t)Cn * Cn / 4 + 255) / 256);
    const unsigned TW = (unsigned)((KP * Cn + 255) / 256);
    const int SHB = 3 * 128 * 40 * 2 * 2;
    const int BSH3 = 1024 + 3 * 32768;
    const int BSH1 = 1024 + 6 * 16384;

    cudaFuncSetAttribute(hgemm2, cudaFuncAttributeMaxDynamicSharedMemorySize, SHB);
    cudaFuncSetAttribute(bgemm3, cudaFuncAttributeMaxDynamicSharedMemorySize, BSH3);
    cudaFuncSetAttribute(bgemm1, cudaFuncAttributeMaxDynamicSharedMemorySize, BSH1);

    // weight prep
    conv_wt4<<<dim3(WW4, 4), 256>>>(W_r, W_k, W_v, W_o);
    tsplit_all<<<dim3(TW, 8), 256>>>(w1, a1, v1, g1, w2, a2, v2, g2);

    // mixing (4-wide)
    mix_split<<<EW4, 256>>>(x, mask, x_r, x_w, x_k, x_v, x_a, x_g);

    // merged: k/v (z0..1) + mlp1 (z2..5) + r fp16 6-stage (z6)
    bgemm3<<<dim3(16, 64, 7), 256, BSH3>>>();

    // mlp2 (4 paths, zero-padding skipped)
    hgemm2<<<dim3(16, 64, 4), 256, SHB>>>(w0, a0, v0);

    // fused v-combine + kk
    kkv_fused<<<BT * Hn / 8, 256>>>(vf, mask, k_k, k_a);

    // scan (prefetch depth 2)
    scan_kernel<<<Bn * Hn, 128>>>();

    // post groupnorm -> fp16 tiled
    postln_kernel<<<BT * Hn / 4, 128>>>(r_k, ln_w, ln_b);

    // output projection: single fp16
    bgemm1<<<dim3(16, 64), 256, BSH1>>>(p_ygt, p_Wo16, out);

    if ((size_t)out_size >= 2 * BTC) {
        cudaMemcpyAsync(out + BTC, vf, BTC * sizeof(float), cudaMemcpyDeviceToDevice, 0);
    }
}